// round 10
// baseline (speedup 1.0000x reference)
#include <cuda_runtime.h>
#include <math.h>

#define NB 4
#define NP 8
#define NR 32
#define IMG 128
#define THW 1024
#define TCH 8
#define TGT 64
#define VMAX 1024
#define FMAX 1024
#define FPAD 1024
#define NSPLIT 4
#define SPLEN (FPAD / NSPLIT)   // 256 triangles per split

// Scratch (static device globals — no runtime allocation)
__device__ float4 g_vert[NR * VMAX];               // px, py, z, iw
__device__ float  g_w[NR * VMAX];                  // clip w
__device__ float4 g_trih[NR * FMAX * 5];           // unsorted hot records
__device__ float4 g_tric[NR * FMAX * 3];           // unsorted cold records
__device__ float  g_key[NR * FPAD];                // sort keys (zmin / INF)
__device__ float4 g_trihs[NR * FPAD * 5];          // sorted (split-major) hot
__device__ float4 g_trics[NR * FPAD * 3];          // sorted (split-major) cold
__device__ float2 g_part[NSPLIT * NR * IMG * IMG]; // (depth, win) partials
__device__ float4 g_rend[NR * IMG * IMG * 2];      // rendered 8ch
__device__ float4 g_uvm[NR * IMG * IMG];           // u, v, mask, mask_rend
__device__ int4   g_rect[NR];                      // live pixel rect per render

// ---------------------------------------------------------------------------
// Kernel A1: vertex transform.  grid (NR, ceil(V/256)), block 256.
// ---------------------------------------------------------------------------
__global__ __launch_bounds__(256) void vertex_kernel(
    const float* __restrict__ vertices, const float* __restrict__ poses,
    const float* __restrict__ bboxes, int V)
{
    int n = blockIdx.x;
    int b = n & (NB - 1);
    int p = n >> 2;
    int v = blockIdx.y * 256 + threadIdx.x;

    if (blockIdx.y == 0 && threadIdx.x == 0) {
        // live rect: pixels crop can validly sample (padded ±1 vs ulp drift)
        const float* bx = bboxes + (size_t)(b * NP + p) * 4;
        float y1 = bx[0], x1 = bx[1], y2 = bx[2], x2 = bx[3];
        int ry0 = max(0, (int)floorf(fmaxf(0.f, y1 * 127.f)) - 1);
        int ry1 = min(127, (int)floorf(fminf(127.f, y2 * 127.f)) + 2);
        int rx0 = max(0, (int)floorf(fmaxf(0.f, x1 * 127.f)) - 1);
        int rx1 = min(127, (int)floorf(fminf(127.f, x2 * 127.f)) + 2);
        g_rect[n] = make_int4(rx0, ry0, rx1, ry1);
    }
    if (v >= V) return;

    const float* ps = poses + (size_t)(b * NP + p) * 16;
    float r0 = ps[0],  r1 = ps[1],  r2 = ps[2],  r3 = ps[3];
    float r4 = -ps[4], r5 = -ps[5], r6 = -ps[6], r7 = -ps[7];
    float r8 = -ps[8], r9 = -ps[9], r10 = -ps[10], r11 = -ps[11];
    float r12 = ps[12], r13 = ps[13], r14 = ps[14], r15 = ps[15];

    const double ncd = 0.1, fcd = 10.0;
    const float Qf  = (float)(-(fcd + ncd) / (fcd - ncd));
    const float QNf = (float)(-2.0 * (fcd * ncd) / (fcd - ncd));
    const float S = 1.875f;  // 2*120/128

    const float* vp = vertices + ((size_t)b * V + v) * 3;
    float X = vp[0], Y = vp[1], Z = vp[2];
    float c0 = ((X * r0  + Y * r1)  + Z * r2)  + r3;
    float c1 = ((X * r4  + Y * r5)  + Z * r6)  + r7;
    float c2 = ((X * r8  + Y * r9)  + Z * r10) + r11;
    float c3 = ((X * r12 + Y * r13) + Z * r14) + r15;
    float clx = c0 * S;
    float cly = c1 * S;
    float clz = c2 * Qf + c3 * QNf;
    float w = -c2;
    float wsafe = (fabsf(w) < 1e-8f) ? 1e-8f : w;
    float ndx = clx / wsafe;
    float ndy = cly / wsafe;
    float ndz = clz / wsafe;
    float px = (ndx * 0.5f + 0.5f) * 128.0f;
    float py = (1.0f - (ndy * 0.5f + 0.5f)) * 128.0f;
    g_vert[(size_t)n * VMAX + v] = make_float4(px, py, ndz, 1.0f / wsafe);
    g_w[(size_t)n * VMAX + v] = w;
}

// ---------------------------------------------------------------------------
// Kernel A2: triangle setup.  grid (NR, FPAD/256), block 256.
// ---------------------------------------------------------------------------
__global__ __launch_bounds__(256) void face_kernel(
    const float* __restrict__ uv_map, const int* __restrict__ faces,
    int V, int F)
{
    int n = blockIdx.x;
    int b = n & (NB - 1);
    int f = blockIdx.y * 256 + threadIdx.x;
    if (f >= FPAD) return;
    if (f >= F) { g_key[(size_t)n * FPAD + f] = INFINITY; return; }

    const float4* verts = g_vert + (size_t)n * VMAX;
    const float*  ws    = g_w    + (size_t)n * VMAX;
    const int* fp = faces + ((size_t)b * F + f) * 3;
    int i0 = fp[0], i1 = fp[1], i2 = fp[2];
    float4 A = verts[i0], Bv = verts[i1], C = verts[i2];
    bool front = (ws[i0] > 1e-8f) && (ws[i1] > 1e-8f) && (ws[i2] > 1e-8f);
    float area = (Bv.x - A.x) * (C.y - A.y) - (Bv.y - A.y) * (C.x - A.x);
    bool valid = front && (fabsf(area) > 1e-9f);
    float a_safe = (fabsf(area) < 1e-9f) ? 1.0f : area;
    float inva = 1.0f / a_safe;
    float s = (inva >= 0.0f) ? 1.0f : -1.0f;   // exact sign fold
    float ainv = fabsf(inva);
    float ex0 = s * (C.x - Bv.x),  ey0 = s * (C.y - Bv.y);
    float ex1 = s * (A.x - C.x),   ey1 = s * (A.y - C.y);
    float ex2 = s * (Bv.x - A.x),  ey2 = s * (Bv.y - A.y);
    float za = A.z * ainv, zb = Bv.z * ainv, zc = C.z * ainv;
    float zmin = fminf(A.z, fminf(Bv.z, C.z));

    const float* uvb = uv_map + (size_t)b * V * 2;
    float u0 = uvb[i0 * 2], vv0 = uvb[i0 * 2 + 1];
    float u1 = uvb[i1 * 2], vv1 = uvb[i1 * 2 + 1];
    float u2 = uvb[i2 * 2], vv2 = uvb[i2 * 2 + 1];

    float bxmin, bymin, bxmax, bymax;
    if (valid) {
        bxmin = fminf(A.x, fminf(Bv.x, C.x)) - 0.5f;
        bxmax = fmaxf(A.x, fmaxf(Bv.x, C.x)) + 0.5f;
        bymin = fminf(A.y, fminf(Bv.y, C.y)) - 0.5f;
        bymax = fmaxf(A.y, fmaxf(Bv.y, C.y)) + 0.5f;
    } else {
        bxmin = 1e30f; bymin = 1e30f; bxmax = -1e30f; bymax = -1e30f;
    }
    float4* h = g_trih + ((size_t)n * FMAX + f) * 5;
    h[0] = make_float4(ex0, ey0, Bv.x, Bv.y);
    h[1] = make_float4(ex1, ey1, C.x, C.y);
    h[2] = make_float4(ex2, ey2, A.x, A.y);
    h[3] = make_float4(bxmin, bymin, bxmax, bymax);
    h[4] = make_float4(za, zb, zc, zmin);
    float4* c = g_tric + ((size_t)n * FMAX + f) * 3;
    c[0] = make_float4(ainv, A.w, Bv.w, C.w);
    c[1] = make_float4(A.w * u0, Bv.w * u1, C.w * u2, 0.0f);
    c[2] = make_float4(A.w * vv0, Bv.w * vv1, C.w * vv2, 0.0f);
    g_key[(size_t)n * FPAD + f] = valid ? zmin : INFINITY;
}

// ---------------------------------------------------------------------------
// Kernel A3: bitonic sort by zmin + permute records to split-major sorted
// order.  grid NR, block 1024.
// ---------------------------------------------------------------------------
__global__ __launch_bounds__(1024) void sort_kernel()
{
    __shared__ float skey[FPAD];
    __shared__ int   sidx[FPAD];
    int n = blockIdx.x;
    int t = threadIdx.x;
    skey[t] = g_key[(size_t)n * FPAD + t];
    sidx[t] = t;
    __syncthreads();

    for (int k = 2; k <= FPAD; k <<= 1) {
        for (int j = k >> 1; j > 0; j >>= 1) {
            int ixj = t ^ j;
            if (ixj > t) {
                bool up = ((t & k) == 0);
                float a = skey[t], c = skey[ixj];
                if ((a > c) == up) {
                    skey[t] = c; skey[ixj] = a;
                    int tmp = sidx[t]; sidx[t] = sidx[ixj]; sidx[ixj] = tmp;
                }
            }
            __syncthreads();
        }
    }

    // permute to split-major: sorted position t -> (split = t&3, slot = t>>2)
    int f = sidx[t];
    int q = (t & (NSPLIT - 1)) * SPLEN + (t >> 2);
    float4* hd = g_trihs + ((size_t)n * FPAD + q) * 5;
    float4* cd = g_trics + ((size_t)n * FPAD + q) * 3;
    if (skey[t] < 1e30f) {
        const float4* hs = g_trih + ((size_t)n * FMAX + f) * 5;
        const float4* cs = g_tric + ((size_t)n * FMAX + f) * 3;
        hd[0] = hs[0]; hd[1] = hs[1]; hd[2] = hs[2]; hd[3] = hs[3]; hd[4] = hs[4];
        cd[0] = cs[0]; cd[1] = cs[1]; cd[2] = cs[2];
    } else {
        float4 z = make_float4(0.f, 0.f, 0.f, 0.f);
        hd[0] = z; hd[1] = z; hd[2] = z;
        hd[3] = make_float4(1e30f, 1e30f, -1e30f, -1e30f);   // empty bbox
        hd[4] = make_float4(0.f, 0.f, 0.f, INFINITY);        // zmin = INF
        cd[0] = make_float4(1.f, 0.f, 0.f, 0.f);
        cd[1] = z; cd[2] = z;
    }
}

// ---------------------------------------------------------------------------
// Kernel B: rasterize partials over depth-sorted triangles with early
// termination.  Block = 128 cols x 8 rows. grid = (16, 32, NSPLIT)
// ---------------------------------------------------------------------------
__global__ __launch_bounds__(128) void raster_kernel()
{
    __shared__ float4 s_tri[128 * 5];
    int n = blockIdx.y;
    int tile = blockIdx.x;
    int split = blockIdx.z;
    int r0 = tile * 8;
    int4 rect = g_rect[n];
    if (r0 > rect.w || r0 + 7 < rect.y) return;   // whole strip dead (uniform)

    int tid = threadIdx.x;            // column
    int lane = tid & 31;
    float gx = tid + 0.5f;
    float gy0 = r0 + 0.5f;
    int warp = tid >> 5;
    float wxmin = fmaxf(warp * 32 + 0.5f, rect.x + 0.5f);
    float wxmax = fminf(warp * 32 + 31.5f, rect.z + 0.5f);
    float rymin = fmaxf(r0 + 0.5f, rect.y + 0.5f);
    float rymax = fminf(r0 + 7.5f, rect.w + 0.5f);
    bool warp_live = (wxmin <= wxmax);
    bool lane_ok = warp_live && (gx >= wxmin) && (gx <= wxmax);
    bool row_ok[8];
#pragma unroll
    for (int r = 0; r < 8; r++) {
        float gy = gy0 + r;
        row_ok[r] = (gy >= rymin) && (gy <= rymax);
    }

    float depth[8];
    int   win[8];
#pragma unroll
    for (int r = 0; r < 8; r++) { depth[r] = INFINITY; win[r] = -1; }

    const float4* trihs = g_trihs + ((size_t)n * FPAD + split * SPLEN) * 5;

    for (int base = 0; base < SPLEN; base += 128) {
        __syncthreads();
        for (int i = tid; i < 128 * 5; i += 128) s_tri[i] = trihs[(size_t)base * 5 + i];
        __syncthreads();

        // stage-level termination vote (valid-pixel-restricted zbound)
        float lmax = -INFINITY;
        if (lane_ok) {
#pragma unroll
            for (int r = 0; r < 8; r++)
                lmax = fmaxf(lmax, row_ok[r] ? depth[r] : -INFINITY);
        }
#pragma unroll
        for (int off = 16; off > 0; off >>= 1)
            lmax = fmaxf(lmax, __shfl_xor_sync(0xffffffffu, lmax, off));
        float zb_stage = fminf(lmax, 1.0f) + 1e-4f;
        int stop = (s_tri[4].w > zb_stage) ? 1 : 0;
        if (__syncthreads_and(stop)) break;

        for (int t0 = 0; t0 < 128; t0 += 32) {
            // per-chunk zbound (tighter than stage-level)
            float cm = -INFINITY;
            if (lane_ok) {
#pragma unroll
                for (int r = 0; r < 8; r++)
                    cm = fmaxf(cm, row_ok[r] ? depth[r] : -INFINITY);
            }
#pragma unroll
            for (int off = 16; off > 0; off >>= 1)
                cm = fmaxf(cm, __shfl_xor_sync(0xffffffffu, cm, off));
            float zbound = fminf(cm, 1.0f) + 1e-4f;

            // sorted: if chunk's first zmin exceeds bound, rest of split too
            if (s_tri[t0 * 5 + 4].w > zbound) { t0 = 128; break; }

            bool pass = false;
            int ti = t0 + lane;
            if (warp_live) {
                float4 bb = s_tri[ti * 5 + 3];
                pass = !(bb.x > wxmax || bb.z < wxmin || bb.y > rymax || bb.w < rymin);
                if (pass) pass = (s_tri[ti * 5 + 4].w <= zbound);
                if (pass) {
                    float4 t0v = s_tri[ti * 5 + 0];
                    float4 t1v = s_tri[ti * 5 + 1];
                    float4 t2v = s_tri[ti * 5 + 2];
                    float y0s = (t0v.x >= 0.f) ? rymax : rymin;
                    float x0s = (t0v.y >= 0.f) ? wxmin : wxmax;
                    float em0 = t0v.x * (y0s - t0v.w) - t0v.y * (x0s - t0v.z);
                    float y1s = (t1v.x >= 0.f) ? rymax : rymin;
                    float x1s = (t1v.y >= 0.f) ? wxmin : wxmax;
                    float em1 = t1v.x * (y1s - t1v.w) - t1v.y * (x1s - t1v.z);
                    float y2s = (t2v.x >= 0.f) ? rymax : rymin;
                    float x2s = (t2v.y >= 0.f) ? wxmin : wxmax;
                    float em2 = t2v.x * (y2s - t2v.w) - t2v.y * (x2s - t2v.z);
                    pass = (em0 >= 0.f) && (em1 >= 0.f) && (em2 >= 0.f);
                }
            }
            unsigned mask = __ballot_sync(0xffffffffu, pass);
            while (mask) {
                int t = __ffs(mask) - 1;
                mask &= mask - 1;
                t += t0;
                float4 f0 = s_tri[t * 5 + 0];
                float4 f1 = s_tri[t * 5 + 1];
                float4 f2 = s_tri[t * 5 + 2];
                float4 f4 = s_tri[t * 5 + 4];
                float e0b = f0.x * (gy0 - f0.w) - f0.y * (gx - f0.z);
                float e1b = f1.x * (gy0 - f1.w) - f1.y * (gx - f1.z);
                float e2b = f2.x * (gy0 - f2.w) - f2.y * (gx - f2.z);
                float zpb = e0b * f4.x + e1b * f4.y + e2b * f4.z;
                float dzp = f0.x * f4.x + f1.x * f4.y + f2.x * f4.z;
                int tg = split * SPLEN + base + t;   // split-major sorted id
#pragma unroll
                for (int r = 0; r < 8; r++) {
                    float rf = (float)r;
                    float e0 = fmaf(rf, f0.x, e0b);
                    float e1 = fmaf(rf, f1.x, e1b);
                    float e2 = fmaf(rf, f2.x, e2b);
                    float zp = fmaf(rf, dzp, zpb);
                    float m  = fminf(fminf(e0, e1), e2);
                    bool upd = (m >= 0.f) && (zp < depth[r]) && (fabsf(zp) <= 1.f);
                    depth[r] = upd ? zp : depth[r];
                    win[r]   = upd ? tg : win[r];
                }
            }
        }
    }

    float2* part = g_part + ((size_t)split * NR + n) * (IMG * IMG);
#pragma unroll
    for (int r = 0; r < 8; r++) {
        int y = r0 + r;
        part[y * IMG + tid] = make_float2(depth[r], __int_as_float(win[r]));
    }
}

// ---------------------------------------------------------------------------
// Kernel B2: merge split partials, resolve winner attrs, texture sample.
// ---------------------------------------------------------------------------
__global__ __launch_bounds__(256) void resolve_kernel(const float* __restrict__ texture)
{
    int gid = blockIdx.x * 256 + threadIdx.x;
    int n = gid >> 14;                 // / (IMG*IMG)
    int pix = gid & (IMG * IMG - 1);
    int px = pix & (IMG - 1);
    int py = pix >> 7;
    int4 rect = g_rect[n];
    if (px < rect.x || px > rect.z || py < rect.y || py > rect.w) return;

    const float2* part = g_part + (size_t)n * (IMG * IMG) + pix;
    float dmin = INFINITY;
    int w = -1;
#pragma unroll
    for (int s = 0; s < NSPLIT; s++) {
        float2 pr = part[(size_t)s * NR * IMG * IMG];
        if (pr.x < dmin) { dmin = pr.x; w = __float_as_int(pr.y); }
    }

    int bidx = n & (NB - 1);
    const float* tex = texture + (size_t)bidx * THW * THW * TCH;
    float4 oa, ob;
    float u = 0.f, v = 0.f;
    float mask = 0.f;
    if (w < 0) {
        // background: u=v=0 -> exact tex[0,0] (weights (1,0,0,0) exactly)
        const float4* t00 = (const float4*)tex;
        oa = t00[0]; ob = t00[1];
    } else {
        mask = 1.f;
        float gx = px + 0.5f;
        float gy = py + 0.5f;
        const float4* trihs = g_trihs + (size_t)n * FPAD * 5;
        const float4* trics = g_trics + (size_t)n * FPAD * 3;
        float4 f0 = trihs[w * 5 + 0];
        float4 f1 = trihs[w * 5 + 1];
        float4 f2 = trihs[w * 5 + 2];
        float4 c0 = trics[w * 3 + 0];
        float4 c1 = trics[w * 3 + 1];
        float4 c2 = trics[w * 3 + 2];
        float e0 = f0.x * (gy - f0.w) - f0.y * (gx - f0.z);
        float e1 = f1.x * (gy - f1.w) - f1.y * (gx - f1.z);
        float e2 = f2.x * (gy - f2.w) - f2.y * (gx - f2.z);
        float b0 = e0 * c0.x, b1 = e1 * c0.x, b2 = e2 * c0.x;
        float pw = b0 * c0.y + b1 * c0.z + b2 * c0.w;
        pw = (fabsf(pw) < 1e-12f) ? 1e-12f : pw;
        float ipw = 1.0f / pw;
        u = (b0 * c1.x + b1 * c1.y + b2 * c1.z) * ipw;
        v = (b0 * c2.x + b1 * c2.y + b2 * c2.z) * ipw;

        float idy = fminf(fmaxf(v, 0.f), 1.f) * 1024.0f;
        float idx = fminf(fmaxf(u, 0.f), 1.f) * 1024.0f;
        float fly = floorf(idy), flx = floorf(idx);
        float fy = idy - fly, fx = idx - flx;
        int i = (int)fly, j = (int)flx;
        int i0 = min(max(i, 0), 1023), j0 = min(max(j, 0), 1023);
        int i1 = min(i + 1, 1023),     j1 = min(j + 1, 1023);
        const float4* t00 = (const float4*)(tex + ((size_t)i0 * 1024 + j0) * 8);
        const float4* t01 = (const float4*)(tex + ((size_t)i0 * 1024 + j1) * 8);
        const float4* t10 = (const float4*)(tex + ((size_t)i1 * 1024 + j0) * 8);
        const float4* t11 = (const float4*)(tex + ((size_t)i1 * 1024 + j1) * 8);
        float w00 = (1.f - fx) * (1.f - fy);
        float w01 = fx * (1.f - fy);
        float w10 = (1.f - fx) * fy;
        float w11 = fx * fy;
        float4 qa00 = t00[0], qb00 = t00[1];
        float4 qa01 = t01[0], qb01 = t01[1];
        float4 qa10 = t10[0], qb10 = t10[1];
        float4 qa11 = t11[0], qb11 = t11[1];
        oa.x = qa00.x * w00 + qa01.x * w01 + qa10.x * w10 + qa11.x * w11;
        oa.y = qa00.y * w00 + qa01.y * w01 + qa10.y * w10 + qa11.y * w11;
        oa.z = qa00.z * w00 + qa01.z * w01 + qa10.z * w10 + qa11.z * w11;
        oa.w = qa00.w * w00 + qa01.w * w01 + qa10.w * w10 + qa11.w * w11;
        ob.x = qb00.x * w00 + qb01.x * w01 + qb10.x * w10 + qb11.x * w11;
        ob.y = qb00.y * w00 + qb01.y * w01 + qb10.y * w10 + qb11.y * w11;
        ob.z = qb00.z * w00 + qb01.z * w01 + qb10.z * w10 + qb11.z * w11;
        ob.w = qb00.w * w00 + qb01.w * w01 + qb10.w * w10 + qb11.w * w11;
    }
    g_rend[(size_t)gid * 2 + 0] = oa;
    g_rend[(size_t)gid * 2 + 1] = ob;
    g_uvm[gid] = make_float4(u, v, mask, ((u + v) > 0.f) ? 1.f : 0.f);
}

// ---------------------------------------------------------------------------
// Kernel C: crop_and_resize (bilinear) + thresholds, one thread per out pixel
// ---------------------------------------------------------------------------
__global__ __launch_bounds__(256) void crop_kernel(const float* __restrict__ bboxes,
                                                   float* __restrict__ out)
{
    int gid = blockIdx.x * 256 + threadIdx.x;
    if (gid >= NR * TGT * TGT) return;
    int n = gid / (TGT * TGT);
    int pix = gid - n * (TGT * TGT);
    int ty = pix / TGT, tx = pix - (pix / TGT) * TGT;
    int b = n & 3, p = n >> 2;
    const float* bx = bboxes + (size_t)(b * NP + p) * 4;
    float y1 = bx[0], x1 = bx[1], y2 = bx[2], x2 = bx[3];
    float stepy = ((y2 - y1) * 127.0f) / 63.0f;
    float stepx = ((x2 - x1) * 127.0f) / 63.0f;
    float ys = y1 * 127.0f + (float)ty * stepy;
    float xs = x1 * 127.0f + (float)tx * stepx;
    bool vy = (ys >= 0.f) && (ys <= 127.f);
    bool vx = (xs >= 0.f) && (xs <= 127.f);
    bool valid = vy && vx;
    float yc = fminf(fmaxf(ys, 0.f), 127.f);
    float xc = fminf(fmaxf(xs, 0.f), 127.f);
    float y0f = floorf(yc), x0f = floorf(xc);
    float fy = yc - y0f, fx = xc - x0f;
    int i0 = (int)y0f, j0 = (int)x0f;
    int i1 = min(i0 + 1, 127), j1 = min(j0 + 1, 127);
    float w00 = (1.f - fy) * (1.f - fx);
    float w01 = (1.f - fy) * fx;
    float w10 = fy * (1.f - fx);
    float w11 = fy * fx;

    size_t ib = (size_t)n * (IMG * IMG);
    float4 m00 = g_uvm[ib + i0 * IMG + j0];
    float4 m01 = g_uvm[ib + i0 * IMG + j1];
    float4 m10 = g_uvm[ib + i1 * IMG + j0];
    float4 m11 = g_uvm[ib + i1 * IMG + j1];
    float4 ra00 = g_rend[(ib + i0 * IMG + j0) * 2],     rb00 = g_rend[(ib + i0 * IMG + j0) * 2 + 1];
    float4 ra01 = g_rend[(ib + i0 * IMG + j1) * 2],     rb01 = g_rend[(ib + i0 * IMG + j1) * 2 + 1];
    float4 ra10 = g_rend[(ib + i1 * IMG + j0) * 2],     rb10 = g_rend[(ib + i1 * IMG + j0) * 2 + 1];
    float4 ra11 = g_rend[(ib + i1 * IMG + j1) * 2],     rb11 = g_rend[(ib + i1 * IMG + j1) * 2 + 1];

    float mnew = m00.w * w00 + m01.w * w01 + m10.w * w10 + m11.w * w11;
    float mold = m00.z * w00 + m01.z * w01 + m10.z * w10 + m11.z * w11;
    float uo   = m00.x * w00 + m01.x * w01 + m10.x * w10 + m11.x * w11;
    float vo   = m00.y * w00 + m01.y * w01 + m10.y * w10 + m11.y * w11;
    float rc[8];
    rc[0] = ra00.x * w00 + ra01.x * w01 + ra10.x * w10 + ra11.x * w11;
    rc[1] = ra00.y * w00 + ra01.y * w01 + ra10.y * w10 + ra11.y * w11;
    rc[2] = ra00.z * w00 + ra01.z * w01 + ra10.z * w10 + ra11.z * w11;
    rc[3] = ra00.w * w00 + ra01.w * w01 + ra10.w * w10 + ra11.w * w11;
    rc[4] = rb00.x * w00 + rb01.x * w01 + rb10.x * w10 + rb11.x * w11;
    rc[5] = rb00.y * w00 + rb01.y * w01 + rb10.y * w10 + rb11.y * w11;
    rc[6] = rb00.z * w00 + rb01.z * w01 + rb10.z * w10 + rb11.z * w11;
    rc[7] = rb00.w * w00 + rb01.w * w01 + rb10.w * w10 + rb11.w * w11;

    float vscale = valid ? 1.0f : 0.0f;
    float4 o0, o1, o2;
    o0.x = (valid && mnew > 0.5f) ? 1.f : 0.f;
    o0.y = rc[0] * vscale;
    o0.z = rc[1] * vscale;
    o0.w = rc[2] * vscale;
    o1.x = rc[3] * vscale;
    o1.y = rc[4] * vscale;
    o1.z = rc[5] * vscale;
    o1.w = rc[6] * vscale;
    o2.x = rc[7] * vscale;
    o2.y = (valid && mold > 0.5f) ? 1.f : 0.f;
    o2.z = uo * vscale;
    o2.w = vo * vscale;
    float4* op = (float4*)(out + (size_t)gid * 12);
    op[0] = o0;
    op[1] = o1;
    op[2] = o2;
}

// ---------------------------------------------------------------------------
extern "C" void kernel_launch(void* const* d_in, const int* in_sizes, int n_in,
                              void* d_out, int out_size)
{
    const float* vertices = (const float*)d_in[0];
    const float* uv_map   = (const float*)d_in[1];
    const int*   faces    = (const int*)d_in[2];
    const float* texture  = (const float*)d_in[3];
    const float* poses    = (const float*)d_in[4];
    const float* bboxes   = (const float*)d_in[5];
    int V = in_sizes[0] / (NB * 3);
    int F = in_sizes[2] / (NB * 3);

    dim3 gV(NR, (V + 255) / 256);
    vertex_kernel<<<gV, 256>>>(vertices, poses, bboxes, V);
    dim3 gF(NR, FPAD / 256);
    face_kernel<<<gF, 256>>>(uv_map, faces, V, F);
    sort_kernel<<<NR, 1024>>>();
    dim3 gB(16, NR, NSPLIT);
    raster_kernel<<<gB, 128>>>();
    int nfull = NR * IMG * IMG;
    resolve_kernel<<<nfull / 256, 256>>>(texture);
    int npix = NR * TGT * TGT;
    crop_kernel<<<(npix + 255) / 256, 256>>>(bboxes, (float*)d_out);
}

// round 11
// speedup vs baseline: 1.0238x; 1.0238x over previous
#include <cuda_runtime.h>
#include <math.h>

#define NB 4
#define NP 8
#define NR 32
#define IMG 128
#define THW 1024
#define TCH 8
#define TGT 64
#define VMAX 1024
#define FMAX 1024
#define FPAD 1024
#define NSPLIT 2
#define SPLEN (FPAD / NSPLIT)   // 512 triangles per split

#define DEPTH_INIT 1.0000001f   // nextafter(1): zp<DEPTH_INIT <=> zp<=1 (1ulp)

// Scratch (static device globals — no runtime allocation)
__device__ float4 g_vert[NR * VMAX];               // px, py, z, iw
__device__ float  g_w[NR * VMAX];                  // clip w
__device__ float4 g_trih[NR * FMAX * 5];           // unsorted hot records
__device__ float4 g_tric[NR * FMAX * 3];           // unsorted cold records
__device__ float  g_key[NR * FPAD];                // sort keys (zmin / INF)
__device__ float4 g_trihs[NR * FPAD * 5];          // sorted (split-major) hot
__device__ float4 g_trics[NR * FPAD * 3];          // sorted (split-major) cold
__device__ float2 g_part[NSPLIT * NR * IMG * IMG]; // (depth, win) partials
__device__ float4 g_rend[NR * IMG * IMG * 2];      // rendered 8ch
__device__ float4 g_uvm[NR * IMG * IMG];           // u, v, mask, mask_rend
__device__ int4   g_rect[NR];                      // live pixel rect per render

// ---------------------------------------------------------------------------
// Kernel A1: vertex transform.  grid (NR, ceil(V/256)), block 256.
// ---------------------------------------------------------------------------
__global__ __launch_bounds__(256) void vertex_kernel(
    const float* __restrict__ vertices, const float* __restrict__ poses,
    const float* __restrict__ bboxes, int V)
{
    int n = blockIdx.x;
    int b = n & (NB - 1);
    int p = n >> 2;
    int v = blockIdx.y * 256 + threadIdx.x;

    if (blockIdx.y == 0 && threadIdx.x == 0) {
        // live rect: pixels crop can validly sample (padded ±1 vs ulp drift)
        const float* bx = bboxes + (size_t)(b * NP + p) * 4;
        float y1 = bx[0], x1 = bx[1], y2 = bx[2], x2 = bx[3];
        int ry0 = max(0, (int)floorf(fmaxf(0.f, y1 * 127.f)) - 1);
        int ry1 = min(127, (int)floorf(fminf(127.f, y2 * 127.f)) + 2);
        int rx0 = max(0, (int)floorf(fmaxf(0.f, x1 * 127.f)) - 1);
        int rx1 = min(127, (int)floorf(fminf(127.f, x2 * 127.f)) + 2);
        g_rect[n] = make_int4(rx0, ry0, rx1, ry1);
    }
    if (v >= V) return;

    const float* ps = poses + (size_t)(b * NP + p) * 16;
    float r0 = ps[0],  r1 = ps[1],  r2 = ps[2],  r3 = ps[3];
    float r4 = -ps[4], r5 = -ps[5], r6 = -ps[6], r7 = -ps[7];
    float r8 = -ps[8], r9 = -ps[9], r10 = -ps[10], r11 = -ps[11];
    float r12 = ps[12], r13 = ps[13], r14 = ps[14], r15 = ps[15];

    const double ncd = 0.1, fcd = 10.0;
    const float Qf  = (float)(-(fcd + ncd) / (fcd - ncd));
    const float QNf = (float)(-2.0 * (fcd * ncd) / (fcd - ncd));
    const float S = 1.875f;  // 2*120/128

    const float* vp = vertices + ((size_t)b * V + v) * 3;
    float X = vp[0], Y = vp[1], Z = vp[2];
    float c0 = ((X * r0  + Y * r1)  + Z * r2)  + r3;
    float c1 = ((X * r4  + Y * r5)  + Z * r6)  + r7;
    float c2 = ((X * r8  + Y * r9)  + Z * r10) + r11;
    float c3 = ((X * r12 + Y * r13) + Z * r14) + r15;
    float clx = c0 * S;
    float cly = c1 * S;
    float clz = c2 * Qf + c3 * QNf;
    float w = -c2;
    float wsafe = (fabsf(w) < 1e-8f) ? 1e-8f : w;
    float ndx = clx / wsafe;
    float ndy = cly / wsafe;
    float ndz = clz / wsafe;
    float px = (ndx * 0.5f + 0.5f) * 128.0f;
    float py = (1.0f - (ndy * 0.5f + 0.5f)) * 128.0f;
    g_vert[(size_t)n * VMAX + v] = make_float4(px, py, ndz, 1.0f / wsafe);
    g_w[(size_t)n * VMAX + v] = w;
}

// ---------------------------------------------------------------------------
// Kernel A2: triangle setup.  grid (NR, FPAD/256), block 256.
// ---------------------------------------------------------------------------
__global__ __launch_bounds__(256) void face_kernel(
    const float* __restrict__ uv_map, const int* __restrict__ faces,
    int V, int F)
{
    int n = blockIdx.x;
    int b = n & (NB - 1);
    int f = blockIdx.y * 256 + threadIdx.x;
    if (f >= FPAD) return;
    if (f >= F) { g_key[(size_t)n * FPAD + f] = INFINITY; return; }

    const float4* verts = g_vert + (size_t)n * VMAX;
    const float*  ws    = g_w    + (size_t)n * VMAX;
    const int* fp = faces + ((size_t)b * F + f) * 3;
    int i0 = fp[0], i1 = fp[1], i2 = fp[2];
    float4 A = verts[i0], Bv = verts[i1], C = verts[i2];
    bool front = (ws[i0] > 1e-8f) && (ws[i1] > 1e-8f) && (ws[i2] > 1e-8f);
    float area = (Bv.x - A.x) * (C.y - A.y) - (Bv.y - A.y) * (C.x - A.x);
    bool valid = front && (fabsf(area) > 1e-9f);
    float a_safe = (fabsf(area) < 1e-9f) ? 1.0f : area;
    float inva = 1.0f / a_safe;
    float s = (inva >= 0.0f) ? 1.0f : -1.0f;   // exact sign fold
    float ainv = fabsf(inva);
    float ex0 = s * (C.x - Bv.x),  ey0 = s * (C.y - Bv.y);
    float ex1 = s * (A.x - C.x),   ey1 = s * (A.y - C.y);
    float ex2 = s * (Bv.x - A.x),  ey2 = s * (Bv.y - A.y);
    float za = A.z * ainv, zb = Bv.z * ainv, zc = C.z * ainv;
    float zmin = fminf(A.z, fminf(Bv.z, C.z));

    const float* uvb = uv_map + (size_t)b * V * 2;
    float u0 = uvb[i0 * 2], vv0 = uvb[i0 * 2 + 1];
    float u1 = uvb[i1 * 2], vv1 = uvb[i1 * 2 + 1];
    float u2 = uvb[i2 * 2], vv2 = uvb[i2 * 2 + 1];

    float bxmin, bymin, bxmax, bymax;
    if (valid) {
        bxmin = fminf(A.x, fminf(Bv.x, C.x)) - 0.5f;
        bxmax = fmaxf(A.x, fmaxf(Bv.x, C.x)) + 0.5f;
        bymin = fminf(A.y, fminf(Bv.y, C.y)) - 0.5f;
        bymax = fmaxf(A.y, fmaxf(Bv.y, C.y)) + 0.5f;
    } else {
        bxmin = 1e30f; bymin = 1e30f; bxmax = -1e30f; bymax = -1e30f;
    }
    float4* h = g_trih + ((size_t)n * FMAX + f) * 5;
    h[0] = make_float4(ex0, ey0, Bv.x, Bv.y);
    h[1] = make_float4(ex1, ey1, C.x, C.y);
    h[2] = make_float4(ex2, ey2, A.x, A.y);
    h[3] = make_float4(bxmin, bymin, bxmax, bymax);
    h[4] = make_float4(za, zb, zc, zmin);
    float4* c = g_tric + ((size_t)n * FMAX + f) * 3;
    c[0] = make_float4(ainv, A.w, Bv.w, C.w);
    c[1] = make_float4(A.w * u0, Bv.w * u1, C.w * u2, 0.0f);
    c[2] = make_float4(A.w * vv0, Bv.w * vv1, C.w * vv2, 0.0f);
    g_key[(size_t)n * FPAD + f] = valid ? zmin : INFINITY;
}

// ---------------------------------------------------------------------------
// Kernel A3: bitonic sort by zmin + permute records to split-major sorted
// order (split = t mod NSPLIT -> each split is a near->far subsequence).
// grid NR, block 1024.
// ---------------------------------------------------------------------------
__global__ __launch_bounds__(1024) void sort_kernel()
{
    __shared__ float skey[FPAD];
    __shared__ int   sidx[FPAD];
    int n = blockIdx.x;
    int t = threadIdx.x;
    skey[t] = g_key[(size_t)n * FPAD + t];
    sidx[t] = t;
    __syncthreads();

    for (int k = 2; k <= FPAD; k <<= 1) {
        for (int j = k >> 1; j > 0; j >>= 1) {
            int ixj = t ^ j;
            if (ixj > t) {
                bool up = ((t & k) == 0);
                float a = skey[t], c = skey[ixj];
                if ((a > c) == up) {
                    skey[t] = c; skey[ixj] = a;
                    int tmp = sidx[t]; sidx[t] = sidx[ixj]; sidx[ixj] = tmp;
                }
            }
            __syncthreads();
        }
    }

    int f = sidx[t];
    int q = (t & (NSPLIT - 1)) * SPLEN + (t >> 1);
    float4* hd = g_trihs + ((size_t)n * FPAD + q) * 5;
    float4* cd = g_trics + ((size_t)n * FPAD + q) * 3;
    if (skey[t] < 1e30f) {
        const float4* hs = g_trih + ((size_t)n * FMAX + f) * 5;
        const float4* cs = g_tric + ((size_t)n * FMAX + f) * 3;
        hd[0] = hs[0]; hd[1] = hs[1]; hd[2] = hs[2]; hd[3] = hs[3]; hd[4] = hs[4];
        cd[0] = cs[0]; cd[1] = cs[1]; cd[2] = cs[2];
    } else {
        float4 z = make_float4(0.f, 0.f, 0.f, 0.f);
        hd[0] = z; hd[1] = z; hd[2] = z;
        hd[3] = make_float4(1e30f, 1e30f, -1e30f, -1e30f);   // empty bbox
        hd[4] = make_float4(0.f, 0.f, 0.f, INFINITY);        // zmin = INF
        cd[0] = make_float4(1.f, 0.f, 0.f, 0.f);
        cd[1] = z; cd[2] = z;
    }
}

// ---------------------------------------------------------------------------
// Kernel B: rasterize partials over depth-sorted triangles with early
// termination.  Block = 128 cols x 8 rows. grid = (16, 32, NSPLIT)
// ---------------------------------------------------------------------------
__global__ __launch_bounds__(128) void raster_kernel()
{
    __shared__ float4 s_tri[128 * 5];
    int n = blockIdx.y;
    int tile = blockIdx.x;
    int split = blockIdx.z;
    int r0 = tile * 8;
    int4 rect = g_rect[n];
    if (r0 > rect.w || r0 + 7 < rect.y) return;   // whole strip dead (uniform)

    int tid = threadIdx.x;            // column
    int lane = tid & 31;
    float gx = tid + 0.5f;
    float gy0 = r0 + 0.5f;
    int warp = tid >> 5;
    float wxmin = fmaxf(warp * 32 + 0.5f, rect.x + 0.5f);
    float wxmax = fminf(warp * 32 + 31.5f, rect.z + 0.5f);
    float rymin = fmaxf(r0 + 0.5f, rect.y + 0.5f);
    float rymax = fminf(r0 + 7.5f, rect.w + 0.5f);
    bool warp_live = (wxmin <= wxmax);
    bool lane_ok = warp_live && (gx >= wxmin) && (gx <= wxmax);
    bool row_ok[8];
#pragma unroll
    for (int r = 0; r < 8; r++) {
        float gy = gy0 + r;
        row_ok[r] = (gy >= rymin) && (gy <= rymax);
    }

    float depth[8];
    int   win[8];
#pragma unroll
    for (int r = 0; r < 8; r++) { depth[r] = DEPTH_INIT; win[r] = -1; }

    const float4* trihs = g_trihs + ((size_t)n * FPAD + split * SPLEN) * 5;

    for (int base = 0; base < SPLEN; base += 128) {
        __syncthreads();
        for (int i = tid; i < 128 * 5; i += 128) s_tri[i] = trihs[(size_t)base * 5 + i];
        __syncthreads();

        // stage-level termination vote (valid-pixel-restricted zbound)
        float lmax = -INFINITY;
        if (lane_ok) {
#pragma unroll
            for (int r = 0; r < 8; r++)
                lmax = fmaxf(lmax, row_ok[r] ? depth[r] : -INFINITY);
        }
#pragma unroll
        for (int off = 16; off > 0; off >>= 1)
            lmax = fmaxf(lmax, __shfl_xor_sync(0xffffffffu, lmax, off));
        float zb_stage = lmax + 1e-4f;
        int stop = (s_tri[4].w > zb_stage) ? 1 : 0;
        if (__syncthreads_and(stop)) break;

        for (int t0 = 0; t0 < 128; t0 += 32) {
            // per-chunk zbound (tighter than stage-level)
            float cm = -INFINITY;
            if (lane_ok) {
#pragma unroll
                for (int r = 0; r < 8; r++)
                    cm = fmaxf(cm, row_ok[r] ? depth[r] : -INFINITY);
            }
#pragma unroll
            for (int off = 16; off > 0; off >>= 1)
                cm = fmaxf(cm, __shfl_xor_sync(0xffffffffu, cm, off));
            float zbound = cm + 1e-4f;

            // sorted: if chunk's first zmin exceeds bound, rest of split too
            if (s_tri[t0 * 5 + 4].w > zbound) break;

            bool pass = false;
            int ti = t0 + lane;
            if (warp_live) {
                float4 bb = s_tri[ti * 5 + 3];
                pass = !(bb.x > wxmax || bb.z < wxmin || bb.y > rymax || bb.w < rymin);
                if (pass) pass = (s_tri[ti * 5 + 4].w <= zbound);
                if (pass) {
                    float4 t0v = s_tri[ti * 5 + 0];
                    float4 t1v = s_tri[ti * 5 + 1];
                    float4 t2v = s_tri[ti * 5 + 2];
                    float y0s = (t0v.x >= 0.f) ? rymax : rymin;
                    float x0s = (t0v.y >= 0.f) ? wxmin : wxmax;
                    float em0 = t0v.x * (y0s - t0v.w) - t0v.y * (x0s - t0v.z);
                    float y1s = (t1v.x >= 0.f) ? rymax : rymin;
                    float x1s = (t1v.y >= 0.f) ? wxmin : wxmax;
                    float em1 = t1v.x * (y1s - t1v.w) - t1v.y * (x1s - t1v.z);
                    float y2s = (t2v.x >= 0.f) ? rymax : rymin;
                    float x2s = (t2v.y >= 0.f) ? wxmin : wxmax;
                    float em2 = t2v.x * (y2s - t2v.w) - t2v.y * (x2s - t2v.z);
                    pass = (em0 >= 0.f) && (em1 >= 0.f) && (em2 >= 0.f);
                }
            }
            unsigned mask = __ballot_sync(0xffffffffu, pass);
            while (mask) {
                int t = __ffs(mask) - 1;
                mask &= mask - 1;
                t += t0;
                float4 f0 = s_tri[t * 5 + 0];
                float4 f1 = s_tri[t * 5 + 1];
                float4 f2 = s_tri[t * 5 + 2];
                float4 f4 = s_tri[t * 5 + 4];
                float e0b = f0.x * (gy0 - f0.w) - f0.y * (gx - f0.z);
                float e1b = f1.x * (gy0 - f1.w) - f1.y * (gx - f1.z);
                float e2b = f2.x * (gy0 - f2.w) - f2.y * (gx - f2.z);
                float zpb = e0b * f4.x + e1b * f4.y + e2b * f4.z;
                float dzp = f0.x * f4.x + f1.x * f4.y + f2.x * f4.z;
                int tg = split * SPLEN + base + t;   // split-major sorted id
#pragma unroll
                for (int r = 0; r < 8; r++) {
                    float rf = (float)r;
                    float e0 = fmaf(rf, f0.x, e0b);
                    float e1 = fmaf(rf, f1.x, e1b);
                    float e2 = fmaf(rf, f2.x, e2b);
                    float zp = fmaf(rf, dzp, zpb);
                    float m  = fminf(fminf(e0, e1), e2);
                    float m2 = fminf(m, zp + 1.0f);      // folds zp >= -1
                    bool upd = (m2 >= 0.f) && (zp < depth[r]);
                    depth[r] = upd ? zp : depth[r];
                    win[r]   = upd ? tg : win[r];
                }
            }
        }
    }

    float2* part = g_part + ((size_t)split * NR + n) * (IMG * IMG);
#pragma unroll
    for (int r = 0; r < 8; r++) {
        int y = r0 + r;
        part[y * IMG + tid] = make_float2(depth[r], __int_as_float(win[r]));
    }
}

// ---------------------------------------------------------------------------
// Kernel B2: merge split partials, resolve winner attrs, texture sample.
// ---------------------------------------------------------------------------
__global__ __launch_bounds__(256) void resolve_kernel(const float* __restrict__ texture)
{
    int gid = blockIdx.x * 256 + threadIdx.x;
    int n = gid >> 14;                 // / (IMG*IMG)
    int pix = gid & (IMG * IMG - 1);
    int px = pix & (IMG - 1);
    int py = pix >> 7;
    int4 rect = g_rect[n];
    if (px < rect.x || px > rect.z || py < rect.y || py > rect.w) return;

    const float2* part = g_part + (size_t)n * (IMG * IMG) + pix;
    float dmin = INFINITY;
    int w = -1;
#pragma unroll
    for (int s = 0; s < NSPLIT; s++) {
        float2 pr = part[(size_t)s * NR * IMG * IMG];
        int wi = __float_as_int(pr.y);
        if (wi >= 0 && pr.x < dmin) { dmin = pr.x; w = wi; }
    }

    int bidx = n & (NB - 1);
    const float* tex = texture + (size_t)bidx * THW * THW * TCH;
    float4 oa, ob;
    float u = 0.f, v = 0.f;
    float mask = 0.f;
    if (w < 0) {
        // background: u=v=0 -> exact tex[0,0] (weights (1,0,0,0) exactly)
        const float4* t00 = (const float4*)tex;
        oa = t00[0]; ob = t00[1];
    } else {
        mask = 1.f;
        float gx = px + 0.5f;
        float gy = py + 0.5f;
        const float4* trihs = g_trihs + (size_t)n * FPAD * 5;
        const float4* trics = g_trics + (size_t)n * FPAD * 3;
        float4 f0 = trihs[w * 5 + 0];
        float4 f1 = trihs[w * 5 + 1];
        float4 f2 = trihs[w * 5 + 2];
        float4 c0 = trics[w * 3 + 0];
        float4 c1 = trics[w * 3 + 1];
        float4 c2 = trics[w * 3 + 2];
        float e0 = f0.x * (gy - f0.w) - f0.y * (gx - f0.z);
        float e1 = f1.x * (gy - f1.w) - f1.y * (gx - f1.z);
        float e2 = f2.x * (gy - f2.w) - f2.y * (gx - f2.z);
        float b0 = e0 * c0.x, b1 = e1 * c0.x, b2 = e2 * c0.x;
        float pw = b0 * c0.y + b1 * c0.z + b2 * c0.w;
        pw = (fabsf(pw) < 1e-12f) ? 1e-12f : pw;
        float ipw = 1.0f / pw;
        u = (b0 * c1.x + b1 * c1.y + b2 * c1.z) * ipw;
        v = (b0 * c2.x + b1 * c2.y + b2 * c2.z) * ipw;

        float idy = fminf(fmaxf(v, 0.f), 1.f) * 1024.0f;
        float idx = fminf(fmaxf(u, 0.f), 1.f) * 1024.0f;
        float fly = floorf(idy), flx = floorf(idx);
        float fy = idy - fly, fx = idx - flx;
        int i = (int)fly, j = (int)flx;
        int i0 = min(max(i, 0), 1023), j0 = min(max(j, 0), 1023);
        int i1 = min(i + 1, 1023),     j1 = min(j + 1, 1023);
        const float4* t00 = (const float4*)(tex + ((size_t)i0 * 1024 + j0) * 8);
        const float4* t01 = (const float4*)(tex + ((size_t)i0 * 1024 + j1) * 8);
        const float4* t10 = (const float4*)(tex + ((size_t)i1 * 1024 + j0) * 8);
        const float4* t11 = (const float4*)(tex + ((size_t)i1 * 1024 + j1) * 8);
        float w00 = (1.f - fx) * (1.f - fy);
        float w01 = fx * (1.f - fy);
        float w10 = (1.f - fx) * fy;
        float w11 = fx * fy;
        float4 qa00 = t00[0], qb00 = t00[1];
        float4 qa01 = t01[0], qb01 = t01[1];
        float4 qa10 = t10[0], qb10 = t10[1];
        float4 qa11 = t11[0], qb11 = t11[1];
        oa.x = qa00.x * w00 + qa01.x * w01 + qa10.x * w10 + qa11.x * w11;
        oa.y = qa00.y * w00 + qa01.y * w01 + qa10.y * w10 + qa11.y * w11;
        oa.z = qa00.z * w00 + qa01.z * w01 + qa10.z * w10 + qa11.z * w11;
        oa.w = qa00.w * w00 + qa01.w * w01 + qa10.w * w10 + qa11.w * w11;
        ob.x = qb00.x * w00 + qb01.x * w01 + qb10.x * w10 + qb11.x * w11;
        ob.y = qb00.y * w00 + qb01.y * w01 + qb10.y * w10 + qb11.y * w11;
        ob.z = qb00.z * w00 + qb01.z * w01 + qb10.z * w10 + qb11.z * w11;
        ob.w = qb00.w * w00 + qb01.w * w01 + qb10.w * w10 + qb11.w * w11;
    }
    g_rend[(size_t)gid * 2 + 0] = oa;
    g_rend[(size_t)gid * 2 + 1] = ob;
    g_uvm[gid] = make_float4(u, v, mask, ((u + v) > 0.f) ? 1.f : 0.f);
}

// ---------------------------------------------------------------------------
// Kernel C: crop_and_resize (bilinear) + thresholds, one thread per out pixel
// ---------------------------------------------------------------------------
__global__ __launch_bounds__(256) void crop_kernel(const float* __restrict__ bboxes,
                                                   float* __restrict__ out)
{
    int gid = blockIdx.x * 256 + threadIdx.x;
    if (gid >= NR * TGT * TGT) return;
    int n = gid / (TGT * TGT);
    int pix = gid - n * (TGT * TGT);
    int ty = pix / TGT, tx = pix - (pix / TGT) * TGT;
    int b = n & 3, p = n >> 2;
    const float* bx = bboxes + (size_t)(b * NP + p) * 4;
    float y1 = bx[0], x1 = bx[1], y2 = bx[2], x2 = bx[3];
    float stepy = ((y2 - y1) * 127.0f) / 63.0f;
    float stepx = ((x2 - x1) * 127.0f) / 63.0f;
    float ys = y1 * 127.0f + (float)ty * stepy;
    float xs = x1 * 127.0f + (float)tx * stepx;
    bool vy = (ys >= 0.f) && (ys <= 127.f);
    bool vx = (xs >= 0.f) && (xs <= 127.f);
    bool valid = vy && vx;
    float yc = fminf(fmaxf(ys, 0.f), 127.f);
    float xc = fminf(fmaxf(xs, 0.f), 127.f);
    float y0f = floorf(yc), x0f = floorf(xc);
    float fy = yc - y0f, fx = xc - x0f;
    int i0 = (int)y0f, j0 = (int)x0f;
    int i1 = min(i0 + 1, 127), j1 = min(j0 + 1, 127);
    float w00 = (1.f - fy) * (1.f - fx);
    float w01 = (1.f - fy) * fx;
    float w10 = fy * (1.f - fx);
    float w11 = fy * fx;

    size_t ib = (size_t)n * (IMG * IMG);
    float4 m00 = g_uvm[ib + i0 * IMG + j0];
    float4 m01 = g_uvm[ib + i0 * IMG + j1];
    float4 m10 = g_uvm[ib + i1 * IMG + j0];
    float4 m11 = g_uvm[ib + i1 * IMG + j1];
    float4 ra00 = g_rend[(ib + i0 * IMG + j0) * 2],     rb00 = g_rend[(ib + i0 * IMG + j0) * 2 + 1];
    float4 ra01 = g_rend[(ib + i0 * IMG + j1) * 2],     rb01 = g_rend[(ib + i0 * IMG + j1) * 2 + 1];
    float4 ra10 = g_rend[(ib + i1 * IMG + j0) * 2],     rb10 = g_rend[(ib + i1 * IMG + j0) * 2 + 1];
    float4 ra11 = g_rend[(ib + i1 * IMG + j1) * 2],     rb11 = g_rend[(ib + i1 * IMG + j1) * 2 + 1];

    float mnew = m00.w * w00 + m01.w * w01 + m10.w * w10 + m11.w * w11;
    float mold = m00.z * w00 + m01.z * w01 + m10.z * w10 + m11.z * w11;
    float uo   = m00.x * w00 + m01.x * w01 + m10.x * w10 + m11.x * w11;
    float vo   = m00.y * w00 + m01.y * w01 + m10.y * w10 + m11.y * w11;
    float rc[8];
    rc[0] = ra00.x * w00 + ra01.x * w01 + ra10.x * w10 + ra11.x * w11;
    rc[1] = ra00.y * w00 + ra01.y * w01 + ra10.y * w10 + ra11.y * w11;
    rc[2] = ra00.z * w00 + ra01.z * w01 + ra10.z * w10 + ra11.z * w11;
    rc[3] = ra00.w * w00 + ra01.w * w01 + ra10.w * w10 + ra11.w * w11;
    rc[4] = rb00.x * w00 + rb01.x * w01 + rb10.x * w10 + rb11.x * w11;
    rc[5] = rb00.y * w00 + rb01.y * w01 + rb10.y * w10 + rb11.y * w11;
    rc[6] = rb00.z * w00 + rb01.z * w01 + rb10.z * w10 + rb11.z * w11;
    rc[7] = rb00.w * w00 + rb01.w * w01 + rb10.w * w10 + rb11.w * w11;

    float vscale = valid ? 1.0f : 0.0f;
    float4 o0, o1, o2;
    o0.x = (valid && mnew > 0.5f) ? 1.f : 0.f;
    o0.y = rc[0] * vscale;
    o0.z = rc[1] * vscale;
    o0.w = rc[2] * vscale;
    o1.x = rc[3] * vscale;
    o1.y = rc[4] * vscale;
    o1.z = rc[5] * vscale;
    o1.w = rc[6] * vscale;
    o2.x = rc[7] * vscale;
    o2.y = (valid && mold > 0.5f) ? 1.f : 0.f;
    o2.z = uo * vscale;
    o2.w = vo * vscale;
    float4* op = (float4*)(out + (size_t)gid * 12);
    op[0] = o0;
    op[1] = o1;
    op[2] = o2;
}

// ---------------------------------------------------------------------------
extern "C" void kernel_launch(void* const* d_in, const int* in_sizes, int n_in,
                              void* d_out, int out_size)
{
    const float* vertices = (const float*)d_in[0];
    const float* uv_map   = (const float*)d_in[1];
    const int*   faces    = (const int*)d_in[2];
    const float* texture  = (const float*)d_in[3];
    const float* poses    = (const float*)d_in[4];
    const float* bboxes   = (const float*)d_in[5];
    int V = in_sizes[0] / (NB * 3);
    int F = in_sizes[2] / (NB * 3);

    dim3 gV(NR, (V + 255) / 256);
    vertex_kernel<<<gV, 256>>>(vertices, poses, bboxes, V);
    dim3 gF(NR, FPAD / 256);
    face_kernel<<<gF, 256>>>(uv_map, faces, V, F);
    sort_kernel<<<NR, 1024>>>();
    dim3 gB(16, NR, NSPLIT);
    raster_kernel<<<gB, 128>>>();
    int nfull = NR * IMG * IMG;
    resolve_kernel<<<nfull / 256, 256>>>(texture);
    int npix = NR * TGT * TGT;
    crop_kernel<<<(npix + 255) / 256, 256>>>(bboxes, (float*)d_out);
}

// round 12
// speedup vs baseline: 1.0750x; 1.0500x over previous
#include <cuda_runtime.h>
#include <math.h>

#define NB 4
#define NP 8
#define NR 32
#define IMG 128
#define THW 1024
#define TCH 8
#define TGT 64
#define VMAX 1024
#define FMAX 1024
#define NSPLIT 4

#define DEPTH_INIT 1.0000001f   // nextafter(1): zp<DEPTH_INIT <=> zp<=1 (1ulp)

// Scratch (static device globals — no runtime allocation)
__device__ float4 g_vert[NR * VMAX];               // px, py, z, iw
__device__ float  g_w[NR * VMAX];                  // clip w
__device__ float4 g_trih[NR * FMAX * 5];           // hot: edges(origin form)/bbox/z
__device__ float4 g_tric[NR * FMAX * 3];           // cold: ainv/iw/uw/vw
__device__ float2 g_part[NSPLIT * NR * IMG * IMG]; // (depth, win) partials
__device__ float4 g_rend[NR * IMG * IMG * 2];      // rendered 8ch
__device__ float4 g_uvm[NR * IMG * IMG];           // u, v, mask, mask_rend
__device__ int4   g_rect[NR];                      // live pixel rect per render

// ---------------------------------------------------------------------------
// Kernel A1: vertex transform.  grid (NR, ceil(V/256)), block 256.
// ---------------------------------------------------------------------------
__global__ __launch_bounds__(256) void vertex_kernel(
    const float* __restrict__ vertices, const float* __restrict__ poses,
    const float* __restrict__ bboxes, int V)
{
    int n = blockIdx.x;
    int b = n & (NB - 1);
    int p = n >> 2;
    int v = blockIdx.y * 256 + threadIdx.x;

    if (blockIdx.y == 0 && threadIdx.x == 0) {
        // live rect: pixels crop can validly sample (padded ±1 vs ulp drift)
        const float* bx = bboxes + (size_t)(b * NP + p) * 4;
        float y1 = bx[0], x1 = bx[1], y2 = bx[2], x2 = bx[3];
        int ry0 = max(0, (int)floorf(fmaxf(0.f, y1 * 127.f)) - 1);
        int ry1 = min(127, (int)floorf(fminf(127.f, y2 * 127.f)) + 2);
        int rx0 = max(0, (int)floorf(fmaxf(0.f, x1 * 127.f)) - 1);
        int rx1 = min(127, (int)floorf(fminf(127.f, x2 * 127.f)) + 2);
        g_rect[n] = make_int4(rx0, ry0, rx1, ry1);
    }
    if (v >= V) return;

    const float* ps = poses + (size_t)(b * NP + p) * 16;
    float r0 = ps[0],  r1 = ps[1],  r2 = ps[2],  r3 = ps[3];
    float r4 = -ps[4], r5 = -ps[5], r6 = -ps[6], r7 = -ps[7];
    float r8 = -ps[8], r9 = -ps[9], r10 = -ps[10], r11 = -ps[11];
    float r12 = ps[12], r13 = ps[13], r14 = ps[14], r15 = ps[15];

    const double ncd = 0.1, fcd = 10.0;
    const float Qf  = (float)(-(fcd + ncd) / (fcd - ncd));
    const float QNf = (float)(-2.0 * (fcd * ncd) / (fcd - ncd));
    const float S = 1.875f;  // 2*120/128

    const float* vp = vertices + ((size_t)b * V + v) * 3;
    float X = vp[0], Y = vp[1], Z = vp[2];
    float c0 = ((X * r0  + Y * r1)  + Z * r2)  + r3;
    float c1 = ((X * r4  + Y * r5)  + Z * r6)  + r7;
    float c2 = ((X * r8  + Y * r9)  + Z * r10) + r11;
    float c3 = ((X * r12 + Y * r13) + Z * r14) + r15;
    float clx = c0 * S;
    float cly = c1 * S;
    float clz = c2 * Qf + c3 * QNf;
    float w = -c2;
    float wsafe = (fabsf(w) < 1e-8f) ? 1e-8f : w;
    float ndx = clx / wsafe;
    float ndy = cly / wsafe;
    float ndz = clz / wsafe;
    float px = (ndx * 0.5f + 0.5f) * 128.0f;
    float py = (1.0f - (ndy * 0.5f + 0.5f)) * 128.0f;
    g_vert[(size_t)n * VMAX + v] = make_float4(px, py, ndz, 1.0f / wsafe);
    g_w[(size_t)n * VMAX + v] = w;
}

// ---------------------------------------------------------------------------
// Kernel A2: triangle setup.  grid (NR, ceil(F/256)), block 256.
// Edges stored in origin form: e(x,y) = ex*y - ey*x + c, c = ey*ax - ex*ay.
// ---------------------------------------------------------------------------
__global__ __launch_bounds__(256) void face_kernel(
    const float* __restrict__ uv_map, const int* __restrict__ faces,
    int V, int F)
{
    int n = blockIdx.x;
    int b = n & (NB - 1);
    int f = blockIdx.y * 256 + threadIdx.x;
    if (f >= F) return;

    const float4* verts = g_vert + (size_t)n * VMAX;
    const float*  ws    = g_w    + (size_t)n * VMAX;
    const int* fp = faces + ((size_t)b * F + f) * 3;
    int i0 = fp[0], i1 = fp[1], i2 = fp[2];
    float4 A = verts[i0], Bv = verts[i1], C = verts[i2];
    bool front = (ws[i0] > 1e-8f) && (ws[i1] > 1e-8f) && (ws[i2] > 1e-8f);
    float area = (Bv.x - A.x) * (C.y - A.y) - (Bv.y - A.y) * (C.x - A.x);
    bool valid = front && (fabsf(area) > 1e-9f);
    float a_safe = (fabsf(area) < 1e-9f) ? 1.0f : area;
    float inva = 1.0f / a_safe;
    float s = (inva >= 0.0f) ? 1.0f : -1.0f;   // exact sign fold
    float ainv = fabsf(inva);
    float ex0 = s * (C.x - Bv.x),  ey0 = s * (C.y - Bv.y);   // anchor v1
    float ex1 = s * (A.x - C.x),   ey1 = s * (A.y - C.y);    // anchor v2
    float ex2 = s * (Bv.x - A.x),  ey2 = s * (Bv.y - A.y);   // anchor v0
    float ec0 = ey0 * Bv.x - ex0 * Bv.y;
    float ec1 = ey1 * C.x  - ex1 * C.y;
    float ec2 = ey2 * A.x  - ex2 * A.y;
    float za = A.z * ainv, zb = Bv.z * ainv, zc = C.z * ainv;
    float zmin = fminf(A.z, fminf(Bv.z, C.z));               // early-z bound

    const float* uvb = uv_map + (size_t)b * V * 2;
    float u0 = uvb[i0 * 2], vv0 = uvb[i0 * 2 + 1];
    float u1 = uvb[i1 * 2], vv1 = uvb[i1 * 2 + 1];
    float u2 = uvb[i2 * 2], vv2 = uvb[i2 * 2 + 1];

    float bxmin, bymin, bxmax, bymax;
    if (valid) {
        bxmin = fminf(A.x, fminf(Bv.x, C.x)) - 0.5f;
        bxmax = fmaxf(A.x, fmaxf(Bv.x, C.x)) + 0.5f;
        bymin = fminf(A.y, fminf(Bv.y, C.y)) - 0.5f;
        bymax = fmaxf(A.y, fmaxf(Bv.y, C.y)) + 0.5f;
    } else {
        bxmin = 1e30f; bymin = 1e30f; bxmax = -1e30f; bymax = -1e30f;
    }
    float4* h = g_trih + ((size_t)n * FMAX + f) * 5;
    h[0] = make_float4(ex0, ey0, ec0, 0.f);
    h[1] = make_float4(ex1, ey1, ec1, 0.f);
    h[2] = make_float4(ex2, ey2, ec2, 0.f);
    h[3] = make_float4(bxmin, bymin, bxmax, bymax);
    h[4] = make_float4(za, zb, zc, zmin);
    float4* c = g_tric + ((size_t)n * FMAX + f) * 3;
    c[0] = make_float4(ainv, A.w, Bv.w, C.w);
    c[1] = make_float4(A.w * u0, Bv.w * u1, C.w * u2, 0.0f);
    c[2] = make_float4(A.w * vv0, Bv.w * vv1, C.w * vv2, 0.0f);
}

// ---------------------------------------------------------------------------
// Kernel B: rasterize partials, live-rect restricted, warp early-z (unsorted).
// Origin-form edges: e = fmaf(ex, y, fmaf(-ey, x, c)).
// Block = 128 cols x 8 rows. grid = (16, 32, NSPLIT)
// ---------------------------------------------------------------------------
__global__ __launch_bounds__(128) void raster_kernel(int F)
{
    __shared__ float4 s_tri[128 * 5];
    int n = blockIdx.y;
    int tile = blockIdx.x;
    int split = blockIdx.z;
    int r0 = tile * 8;
    int4 rect = g_rect[n];
    if (r0 > rect.w || r0 + 7 < rect.y) return;   // whole strip dead (uniform)

    int tid = threadIdx.x;            // column
    int lane = tid & 31;
    float gx = tid + 0.5f;
    float gy0 = r0 + 0.5f;
    int warp = tid >> 5;
    float wxmin = fmaxf(warp * 32 + 0.5f, rect.x + 0.5f);
    float wxmax = fminf(warp * 32 + 31.5f, rect.z + 0.5f);
    float rymin = fmaxf(r0 + 0.5f, rect.y + 0.5f);
    float rymax = fminf(r0 + 7.5f, rect.w + 0.5f);
    bool warp_live = (wxmin <= wxmax);
    bool lane_ok = warp_live && (gx >= wxmin) && (gx <= wxmax);
    bool row_ok[8];
#pragma unroll
    for (int r = 0; r < 8; r++) {
        float gy = gy0 + r;
        row_ok[r] = (gy >= rymin) && (gy <= rymax);
    }

    float depth[8];
    int   win[8];
#pragma unroll
    for (int r = 0; r < 8; r++) { depth[r] = DEPTH_INIT; win[r] = -1; }

    int fbeg = (F * split) / NSPLIT;
    int fend = (F * (split + 1)) / NSPLIT;

    const float4* trih = g_trih + (size_t)n * FMAX * 5;
    for (int base = fbeg; base < fend; base += 128) {
        int cnt = min(128, fend - base);
        __syncthreads();
        for (int i = tid; i < cnt * 5; i += 128) s_tri[i] = trih[(size_t)base * 5 + i];
        __syncthreads();
        for (int t0 = 0; t0 < cnt; t0 += 32) {
            // early-z bound over valid pixels only
            float cm = -INFINITY;
            if (lane_ok) {
#pragma unroll
                for (int r = 0; r < 8; r++)
                    cm = fmaxf(cm, row_ok[r] ? depth[r] : -INFINITY);
            }
#pragma unroll
            for (int off = 16; off > 0; off >>= 1)
                cm = fmaxf(cm, __shfl_xor_sync(0xffffffffu, cm, off));
            float zbound = cm + 1e-4f;   // slack: reject-only-safe

            bool pass = false;
            int ti = t0 + lane;
            if (warp_live && ti < cnt) {
                float4 bb = s_tri[ti * 5 + 3];
                pass = !(bb.x > wxmax || bb.z < wxmin || bb.y > rymax || bb.w < rymin);
                if (pass) pass = (s_tri[ti * 5 + 4].w <= zbound);
                if (pass) {
                    float4 t0v = s_tri[ti * 5 + 0];
                    float4 t1v = s_tri[ti * 5 + 1];
                    float4 t2v = s_tri[ti * 5 + 2];
                    // e max over rect at sign-selected corner
                    float y0s = (t0v.x >= 0.f) ? rymax : rymin;
                    float x0s = (t0v.y >= 0.f) ? wxmin : wxmax;
                    float em0 = fmaf(t0v.x, y0s, fmaf(-t0v.y, x0s, t0v.z));
                    float y1s = (t1v.x >= 0.f) ? rymax : rymin;
                    float x1s = (t1v.y >= 0.f) ? wxmin : wxmax;
                    float em1 = fmaf(t1v.x, y1s, fmaf(-t1v.y, x1s, t1v.z));
                    float y2s = (t2v.x >= 0.f) ? rymax : rymin;
                    float x2s = (t2v.y >= 0.f) ? wxmin : wxmax;
                    float em2 = fmaf(t2v.x, y2s, fmaf(-t2v.y, x2s, t2v.z));
                    pass = (em0 >= 0.f) && (em1 >= 0.f) && (em2 >= 0.f);
                }
            }
            unsigned mask = __ballot_sync(0xffffffffu, pass);
            while (mask) {
                int t = __ffs(mask) - 1;
                mask &= mask - 1;
                t += t0;
                float4 f0 = s_tri[t * 5 + 0];
                float4 f1 = s_tri[t * 5 + 1];
                float4 f2 = s_tri[t * 5 + 2];
                float4 f4 = s_tri[t * 5 + 4];
                float e0b = fmaf(f0.x, gy0, fmaf(-f0.y, gx, f0.z));
                float e1b = fmaf(f1.x, gy0, fmaf(-f1.y, gx, f1.z));
                float e2b = fmaf(f2.x, gy0, fmaf(-f2.y, gx, f2.z));
                float zpb = e0b * f4.x + e1b * f4.y + e2b * f4.z;
                float dzp = f0.x * f4.x + f1.x * f4.y + f2.x * f4.z;
                int tg = base + t;
#pragma unroll
                for (int r = 0; r < 8; r++) {
                    float rf = (float)r;
                    float e0 = fmaf(rf, f0.x, e0b);
                    float e1 = fmaf(rf, f1.x, e1b);
                    float e2 = fmaf(rf, f2.x, e2b);
                    float zp = fmaf(rf, dzp, zpb);
                    float m  = fminf(fminf(e0, e1), e2);
                    float m2 = fminf(m, zp + 1.0f);      // folds zp >= -1
                    bool upd = (m2 >= 0.f) && (zp < depth[r]);
                    depth[r] = upd ? zp : depth[r];
                    win[r]   = upd ? tg : win[r];
                }
            }
        }
    }

    float2* part = g_part + ((size_t)split * NR + n) * (IMG * IMG);
#pragma unroll
    for (int r = 0; r < 8; r++) {
        int y = r0 + r;
        part[y * IMG + tid] = make_float2(depth[r], __int_as_float(win[r]));
    }
}

// ---------------------------------------------------------------------------
// Kernel B2: merge split partials, resolve winner attrs, texture sample.
// ---------------------------------------------------------------------------
__global__ __launch_bounds__(256) void resolve_kernel(const float* __restrict__ texture)
{
    int gid = blockIdx.x * 256 + threadIdx.x;
    int n = gid >> 14;                 // / (IMG*IMG)
    int pix = gid & (IMG * IMG - 1);
    int px = pix & (IMG - 1);
    int py = pix >> 7;
    int4 rect = g_rect[n];
    if (px < rect.x || px > rect.z || py < rect.y || py > rect.w) return;

    const float2* part = g_part + (size_t)n * (IMG * IMG) + pix;
    float dmin = INFINITY;
    int w = -1;
#pragma unroll
    for (int s = 0; s < NSPLIT; s++) {
        float2 pr = part[(size_t)s * NR * IMG * IMG];
        int wi = __float_as_int(pr.y);
        if (wi >= 0 && pr.x < dmin) { dmin = pr.x; w = wi; }
    }

    int bidx = n & (NB - 1);
    const float* tex = texture + (size_t)bidx * THW * THW * TCH;
    float4 oa, ob;
    float u = 0.f, v = 0.f;
    float mask = 0.f;
    if (w < 0) {
        // background: u=v=0 -> exact tex[0,0] (weights (1,0,0,0) exactly)
        const float4* t00 = (const float4*)tex;
        oa = t00[0]; ob = t00[1];
    } else {
        mask = 1.f;
        float gx = px + 0.5f;
        float gy = py + 0.5f;
        const float4* trih = g_trih + (size_t)n * FMAX * 5;
        const float4* tric = g_tric + (size_t)n * FMAX * 3;
        float4 f0 = trih[w * 5 + 0];
        float4 f1 = trih[w * 5 + 1];
        float4 f2 = trih[w * 5 + 2];
        float4 c0 = tric[w * 3 + 0];
        float4 c1 = tric[w * 3 + 1];
        float4 c2 = tric[w * 3 + 2];
        float e0 = fmaf(f0.x, gy, fmaf(-f0.y, gx, f0.z));
        float e1 = fmaf(f1.x, gy, fmaf(-f1.y, gx, f1.z));
        float e2 = fmaf(f2.x, gy, fmaf(-f2.y, gx, f2.z));
        float b0 = e0 * c0.x, b1 = e1 * c0.x, b2 = e2 * c0.x;
        float pw = b0 * c0.y + b1 * c0.z + b2 * c0.w;
        pw = (fabsf(pw) < 1e-12f) ? 1e-12f : pw;
        float ipw = 1.0f / pw;
        u = (b0 * c1.x + b1 * c1.y + b2 * c1.z) * ipw;
        v = (b0 * c2.x + b1 * c2.y + b2 * c2.z) * ipw;

        float idy = fminf(fmaxf(v, 0.f), 1.f) * 1024.0f;
        float idx = fminf(fmaxf(u, 0.f), 1.f) * 1024.0f;
        float fly = floorf(idy), flx = floorf(idx);
        float fy = idy - fly, fx = idx - flx;
        int i = (int)fly, j = (int)flx;
        int i0 = min(max(i, 0), 1023), j0 = min(max(j, 0), 1023);
        int i1 = min(i + 1, 1023),     j1 = min(j + 1, 1023);
        const float4* t00 = (const float4*)(tex + ((size_t)i0 * 1024 + j0) * 8);
        const float4* t01 = (const float4*)(tex + ((size_t)i0 * 1024 + j1) * 8);
        const float4* t10 = (const float4*)(tex + ((size_t)i1 * 1024 + j0) * 8);
        const float4* t11 = (const float4*)(tex + ((size_t)i1 * 1024 + j1) * 8);
        float w00 = (1.f - fx) * (1.f - fy);
        float w01 = fx * (1.f - fy);
        float w10 = (1.f - fx) * fy;
        float w11 = fx * fy;
        float4 qa00 = t00[0], qb00 = t00[1];
        float4 qa01 = t01[0], qb01 = t01[1];
        float4 qa10 = t10[0], qb10 = t10[1];
        float4 qa11 = t11[0], qb11 = t11[1];
        oa.x = qa00.x * w00 + qa01.x * w01 + qa10.x * w10 + qa11.x * w11;
        oa.y = qa00.y * w00 + qa01.y * w01 + qa10.y * w10 + qa11.y * w11;
        oa.z = qa00.z * w00 + qa01.z * w01 + qa10.z * w10 + qa11.z * w11;
        oa.w = qa00.w * w00 + qa01.w * w01 + qa10.w * w10 + qa11.w * w11;
        ob.x = qb00.x * w00 + qb01.x * w01 + qb10.x * w10 + qb11.x * w11;
        ob.y = qb00.y * w00 + qb01.y * w01 + qb10.y * w10 + qb11.y * w11;
        ob.z = qb00.z * w00 + qb01.z * w01 + qb10.z * w10 + qb11.z * w11;
        ob.w = qb00.w * w00 + qb01.w * w01 + qb10.w * w10 + qb11.w * w11;
    }
    g_rend[(size_t)gid * 2 + 0] = oa;
    g_rend[(size_t)gid * 2 + 1] = ob;
    g_uvm[gid] = make_float4(u, v, mask, ((u + v) > 0.f) ? 1.f : 0.f);
}

// ---------------------------------------------------------------------------
// Kernel C: crop_and_resize (bilinear) + thresholds, one thread per out pixel
// ---------------------------------------------------------------------------
__global__ __launch_bounds__(256) void crop_kernel(const float* __restrict__ bboxes,
                                                   float* __restrict__ out)
{
    int gid = blockIdx.x * 256 + threadIdx.x;
    if (gid >= NR * TGT * TGT) return;
    int n = gid / (TGT * TGT);
    int pix = gid - n * (TGT * TGT);
    int ty = pix / TGT, tx = pix - (pix / TGT) * TGT;
    int b = n & 3, p = n >> 2;
    const float* bx = bboxes + (size_t)(b * NP + p) * 4;
    float y1 = bx[0], x1 = bx[1], y2 = bx[2], x2 = bx[3];
    float stepy = ((y2 - y1) * 127.0f) / 63.0f;
    float stepx = ((x2 - x1) * 127.0f) / 63.0f;
    float ys = y1 * 127.0f + (float)ty * stepy;
    float xs = x1 * 127.0f + (float)tx * stepx;
    bool vy = (ys >= 0.f) && (ys <= 127.f);
    bool vx = (xs >= 0.f) && (xs <= 127.f);
    bool valid = vy && vx;
    float yc = fminf(fmaxf(ys, 0.f), 127.f);
    float xc = fminf(fmaxf(xs, 0.f), 127.f);
    float y0f = floorf(yc), x0f = floorf(xc);
    float fy = yc - y0f, fx = xc - x0f;
    int i0 = (int)y0f, j0 = (int)x0f;
    int i1 = min(i0 + 1, 127), j1 = min(j0 + 1, 127);
    float w00 = (1.f - fy) * (1.f - fx);
    float w01 = (1.f - fy) * fx;
    float w10 = fy * (1.f - fx);
    float w11 = fy * fx;

    size_t ib = (size_t)n * (IMG * IMG);
    float4 m00 = g_uvm[ib + i0 * IMG + j0];
    float4 m01 = g_uvm[ib + i0 * IMG + j1];
    float4 m10 = g_uvm[ib + i1 * IMG + j0];
    float4 m11 = g_uvm[ib + i1 * IMG + j1];
    float4 ra00 = g_rend[(ib + i0 * IMG + j0) * 2],     rb00 = g_rend[(ib + i0 * IMG + j0) * 2 + 1];
    float4 ra01 = g_rend[(ib + i0 * IMG + j1) * 2],     rb01 = g_rend[(ib + i0 * IMG + j1) * 2 + 1];
    float4 ra10 = g_rend[(ib + i1 * IMG + j0) * 2],     rb10 = g_rend[(ib + i1 * IMG + j0) * 2 + 1];
    float4 ra11 = g_rend[(ib + i1 * IMG + j1) * 2],     rb11 = g_rend[(ib + i1 * IMG + j1) * 2 + 1];

    float mnew = m00.w * w00 + m01.w * w01 + m10.w * w10 + m11.w * w11;
    float mold = m00.z * w00 + m01.z * w01 + m10.z * w10 + m11.z * w11;
    float uo   = m00.x * w00 + m01.x * w01 + m10.x * w10 + m11.x * w11;
    float vo   = m00.y * w00 + m01.y * w01 + m10.y * w10 + m11.y * w11;
    float rc[8];
    rc[0] = ra00.x * w00 + ra01.x * w01 + ra10.x * w10 + ra11.x * w11;
    rc[1] = ra00.y * w00 + ra01.y * w01 + ra10.y * w10 + ra11.y * w11;
    rc[2] = ra00.z * w00 + ra01.z * w01 + ra10.z * w10 + ra11.z * w11;
    rc[3] = ra00.w * w00 + ra01.w * w01 + ra10.w * w10 + ra11.w * w11;
    rc[4] = rb00.x * w00 + rb01.x * w01 + rb10.x * w10 + rb11.x * w11;
    rc[5] = rb00.y * w00 + rb01.y * w01 + rb10.y * w10 + rb11.y * w11;
    rc[6] = rb00.z * w00 + rb01.z * w01 + rb10.z * w10 + rb11.z * w11;
    rc[7] = rb00.w * w00 + rb01.w * w01 + rb10.w * w10 + rb11.w * w11;

    float vscale = valid ? 1.0f : 0.0f;
    float4 o0, o1, o2;
    o0.x = (valid && mnew > 0.5f) ? 1.f : 0.f;
    o0.y = rc[0] * vscale;
    o0.z = rc[1] * vscale;
    o0.w = rc[2] * vscale;
    o1.x = rc[3] * vscale;
    o1.y = rc[4] * vscale;
    o1.z = rc[5] * vscale;
    o1.w = rc[6] * vscale;
    o2.x = rc[7] * vscale;
    o2.y = (valid && mold > 0.5f) ? 1.f : 0.f;
    o2.z = uo * vscale;
    o2.w = vo * vscale;
    float4* op = (float4*)(out + (size_t)gid * 12);
    op[0] = o0;
    op[1] = o1;
    op[2] = o2;
}

// ---------------------------------------------------------------------------
extern "C" void kernel_launch(void* const* d_in, const int* in_sizes, int n_in,
                              void* d_out, int out_size)
{
    const float* vertices = (const float*)d_in[0];
    const float* uv_map   = (const float*)d_in[1];
    const int*   faces    = (const int*)d_in[2];
    const float* texture  = (const float*)d_in[3];
    const float* poses    = (const float*)d_in[4];
    const float* bboxes   = (const float*)d_in[5];
    int V = in_sizes[0] / (NB * 3);
    int F = in_sizes[2] / (NB * 3);

    dim3 gV(NR, (V + 255) / 256);
    vertex_kernel<<<gV, 256>>>(vertices, poses, bboxes, V);
    dim3 gF(NR, (F + 255) / 256);
    face_kernel<<<gF, 256>>>(uv_map, faces, V, F);
    dim3 gB(16, NR, NSPLIT);
    raster_kernel<<<gB, 128>>>(F);
    int nfull = NR * IMG * IMG;
    resolve_kernel<<<nfull / 256, 256>>>(texture);
    int npix = NR * TGT * TGT;
    crop_kernel<<<(npix + 255) / 256, 256>>>(bboxes, (float*)d_out);
}

// round 15
// speedup vs baseline: 1.2275x; 1.1418x over previous
#include <cuda_runtime.h>
#include <math.h>

#define NB 4
#define NP 8
#define NR 32
#define IMG 128
#define THW 1024
#define TCH 8
#define TGT 64
#define VMAX 1024
#define FMAX 1024
#define NSPLIT 4

#define DEPTH_INIT 1.0000001f   // nextafter(1): zp<DEPTH_INIT <=> zp<=1 (1ulp)

// Scratch (static device globals — no runtime allocation)
__device__ float4 g_vert[NR * VMAX];               // px, py, z, iw
__device__ float  g_w[NR * VMAX];                  // clip w
__device__ float4 g_trih[NR * FMAX * 5];           // hot: edges(origin)/zplane/bbox/z
__device__ float4 g_tric[NR * FMAX * 3];           // cold: ainv/iw/uw/vw
__device__ float2 g_part[NSPLIT * NR * IMG * IMG]; // (depth, win) partials
__device__ float4 g_rend[NR * IMG * IMG * 2];      // rendered 8ch
__device__ float4 g_uvm[NR * IMG * IMG];           // u, v, mask, mask_rend
__device__ int4   g_rect[NR];                      // live pixel rect per render

// ---------------------------------------------------------------------------
// Kernel A1: vertex transform.  grid (NR, ceil(V/256)), block 256.
// ---------------------------------------------------------------------------
__global__ __launch_bounds__(256) void vertex_kernel(
    const float* __restrict__ vertices, const float* __restrict__ poses,
    const float* __restrict__ bboxes, int V)
{
    int n = blockIdx.x;
    int b = n & (NB - 1);
    int p = n >> 2;
    int v = blockIdx.y * 256 + threadIdx.x;

    if (blockIdx.y == 0 && threadIdx.x == 0) {
        // live rect: pixels crop can validly sample (padded ±1 vs ulp drift)
        const float* bx = bboxes + (size_t)(b * NP + p) * 4;
        float y1 = bx[0], x1 = bx[1], y2 = bx[2], x2 = bx[3];
        int ry0 = max(0, (int)floorf(fmaxf(0.f, y1 * 127.f)) - 1);
        int ry1 = min(127, (int)floorf(fminf(127.f, y2 * 127.f)) + 2);
        int rx0 = max(0, (int)floorf(fmaxf(0.f, x1 * 127.f)) - 1);
        int rx1 = min(127, (int)floorf(fminf(127.f, x2 * 127.f)) + 2);
        g_rect[n] = make_int4(rx0, ry0, rx1, ry1);
    }
    if (v >= V) return;

    const float* ps = poses + (size_t)(b * NP + p) * 16;
    float r0 = ps[0],  r1 = ps[1],  r2 = ps[2],  r3 = ps[3];
    float r4 = -ps[4], r5 = -ps[5], r6 = -ps[6], r7 = -ps[7];
    float r8 = -ps[8], r9 = -ps[9], r10 = -ps[10], r11 = -ps[11];
    float r12 = ps[12], r13 = ps[13], r14 = ps[14], r15 = ps[15];

    const double ncd = 0.1, fcd = 10.0;
    const float Qf  = (float)(-(fcd + ncd) / (fcd - ncd));
    const float QNf = (float)(-2.0 * (fcd * ncd) / (fcd - ncd));
    const float S = 1.875f;  // 2*120/128

    const float* vp = vertices + ((size_t)b * V + v) * 3;
    float X = vp[0], Y = vp[1], Z = vp[2];
    float c0 = ((X * r0  + Y * r1)  + Z * r2)  + r3;
    float c1 = ((X * r4  + Y * r5)  + Z * r6)  + r7;
    float c2 = ((X * r8  + Y * r9)  + Z * r10) + r11;
    float c3 = ((X * r12 + Y * r13) + Z * r14) + r15;
    float clx = c0 * S;
    float cly = c1 * S;
    float clz = c2 * Qf + c3 * QNf;
    float w = -c2;
    float wsafe = (fabsf(w) < 1e-8f) ? 1e-8f : w;
    float ndx = clx / wsafe;
    float ndy = cly / wsafe;
    float ndz = clz / wsafe;
    float px = (ndx * 0.5f + 0.5f) * 128.0f;
    float py = (1.0f - (ndy * 0.5f + 0.5f)) * 128.0f;
    g_vert[(size_t)n * VMAX + v] = make_float4(px, py, ndz, 1.0f / wsafe);
    g_w[(size_t)n * VMAX + v] = w;
}

// ---------------------------------------------------------------------------
// Kernel A2: triangle setup.  grid (NR, ceil(F/256)), block 256.
// Edges in origin form: e(x,y) = ex*y - ey*x + c.  z-plane form
// (dzdx, dzdy, z0) packed in the edge records' w slots for rect-z culling.
// ---------------------------------------------------------------------------
__global__ __launch_bounds__(256) void face_kernel(
    const float* __restrict__ uv_map, const int* __restrict__ faces,
    int V, int F)
{
    int n = blockIdx.x;
    int b = n & (NB - 1);
    int f = blockIdx.y * 256 + threadIdx.x;
    if (f >= F) return;

    const float4* verts = g_vert + (size_t)n * VMAX;
    const float*  ws    = g_w    + (size_t)n * VMAX;
    const int* fp = faces + ((size_t)b * F + f) * 3;
    int i0 = fp[0], i1 = fp[1], i2 = fp[2];
    float4 A = verts[i0], Bv = verts[i1], C = verts[i2];
    bool front = (ws[i0] > 1e-8f) && (ws[i1] > 1e-8f) && (ws[i2] > 1e-8f);
    float area = (Bv.x - A.x) * (C.y - A.y) - (Bv.y - A.y) * (C.x - A.x);
    bool valid = front && (fabsf(area) > 1e-9f);
    float a_safe = (fabsf(area) < 1e-9f) ? 1.0f : area;
    float inva = 1.0f / a_safe;
    float s = (inva >= 0.0f) ? 1.0f : -1.0f;   // exact sign fold
    float ainv = fabsf(inva);
    float ex0 = s * (C.x - Bv.x),  ey0 = s * (C.y - Bv.y);   // anchor v1
    float ex1 = s * (A.x - C.x),   ey1 = s * (A.y - C.y);    // anchor v2
    float ex2 = s * (Bv.x - A.x),  ey2 = s * (Bv.y - A.y);   // anchor v0
    float ec0 = ey0 * Bv.x - ex0 * Bv.y;
    float ec1 = ey1 * C.x  - ex1 * C.y;
    float ec2 = ey2 * A.x  - ex2 * A.y;
    float za = A.z * ainv, zb = Bv.z * ainv, zc = C.z * ainv;
    float zmin = fminf(A.z, fminf(Bv.z, C.z));               // global z bound
    // z plane form: zp(x,y) = dzdx*x + dzdy*y + z0
    float dzdy = ex0 * za + ex1 * zb + ex2 * zc;
    float dzdx = -(ey0 * za + ey1 * zb + ey2 * zc);
    float z0   = ec0 * za + ec1 * zb + ec2 * zc;

    const float* uvb = uv_map + (size_t)b * V * 2;
    float u0 = uvb[i0 * 2], vv0 = uvb[i0 * 2 + 1];
    float u1 = uvb[i1 * 2], vv1 = uvb[i1 * 2 + 1];
    float u2 = uvb[i2 * 2], vv2 = uvb[i2 * 2 + 1];

    float bxmin, bymin, bxmax, bymax;
    if (valid) {
        bxmin = fminf(A.x, fminf(Bv.x, C.x)) - 0.5f;
        bxmax = fmaxf(A.x, fmaxf(Bv.x, C.x)) + 0.5f;
        bymin = fminf(A.y, fminf(Bv.y, C.y)) - 0.5f;
        bymax = fmaxf(A.y, fmaxf(Bv.y, C.y)) + 0.5f;
    } else {
        bxmin = 1e30f; bymin = 1e30f; bxmax = -1e30f; bymax = -1e30f;
    }
    float4* h = g_trih + ((size_t)n * FMAX + f) * 5;
    h[0] = make_float4(ex0, ey0, ec0, dzdx);
    h[1] = make_float4(ex1, ey1, ec1, dzdy);
    h[2] = make_float4(ex2, ey2, ec2, z0);
    h[3] = make_float4(bxmin, bymin, bxmax, bymax);
    h[4] = make_float4(za, zb, zc, zmin);
    float4* c = g_tric + ((size_t)n * FMAX + f) * 3;
    c[0] = make_float4(ainv, A.w, Bv.w, C.w);
    c[1] = make_float4(A.w * u0, Bv.w * u1, C.w * u2, 0.0f);
    c[2] = make_float4(A.w * vv0, Bv.w * vv1, C.w * vv2, 0.0f);
}

// ---------------------------------------------------------------------------
// Kernel B: rasterize partials, live-rect restricted, warp early-z with
// rect-corner z-minimum cull (conservative, reject-only).
// Block = 128 cols x 8 rows. grid = (16, 32, NSPLIT)
// ---------------------------------------------------------------------------
__global__ __launch_bounds__(128) void raster_kernel(int F)
{
    __shared__ float4 s_tri[128 * 5];
    int n = blockIdx.y;
    int tile = blockIdx.x;
    int split = blockIdx.z;
    int r0 = tile * 8;
    int4 rect = g_rect[n];
    if (r0 > rect.w || r0 + 7 < rect.y) return;   // whole strip dead (uniform)

    int tid = threadIdx.x;            // column
    int lane = tid & 31;
    float gx = tid + 0.5f;
    float gy0 = r0 + 0.5f;
    int warp = tid >> 5;
    float wxmin = fmaxf(warp * 32 + 0.5f, rect.x + 0.5f);
    float wxmax = fminf(warp * 32 + 31.5f, rect.z + 0.5f);
    float rymin = fmaxf(r0 + 0.5f, rect.y + 0.5f);
    float rymax = fminf(r0 + 7.5f, rect.w + 0.5f);
    bool warp_live = (wxmin <= wxmax);
    bool lane_ok = warp_live && (gx >= wxmin) && (gx <= wxmax);
    bool row_ok[8];
#pragma unroll
    for (int r = 0; r < 8; r++) {
        float gy = gy0 + r;
        row_ok[r] = (gy >= rymin) && (gy <= rymax);
    }

    float depth[8];
    int   win[8];
#pragma unroll
    for (int r = 0; r < 8; r++) { depth[r] = DEPTH_INIT; win[r] = -1; }

    int fbeg = (F * split) / NSPLIT;
    int fend = (F * (split + 1)) / NSPLIT;

    const float4* trih = g_trih + (size_t)n * FMAX * 5;
    for (int base = fbeg; base < fend; base += 128) {
        int cnt = min(128, fend - base);
        __syncthreads();
        for (int i = tid; i < cnt * 5; i += 128) s_tri[i] = trih[(size_t)base * 5 + i];
        __syncthreads();
        for (int t0 = 0; t0 < cnt; t0 += 32) {
            // early-z bound over valid pixels only
            float cm = -INFINITY;
            if (lane_ok) {
#pragma unroll
                for (int r = 0; r < 8; r++)
                    cm = fmaxf(cm, row_ok[r] ? depth[r] : -INFINITY);
            }
#pragma unroll
            for (int off = 16; off > 0; off >>= 1)
                cm = fmaxf(cm, __shfl_xor_sync(0xffffffffu, cm, off));
            float zbound = cm + 1e-4f;   // slack: reject-only-safe

            bool pass = false;
            int ti = t0 + lane;
            if (warp_live && ti < cnt) {
                float4 bb = s_tri[ti * 5 + 3];
                pass = !(bb.x > wxmax || bb.z < wxmin || bb.y > rymax || bb.w < rymin);
                if (pass) {
                    float4 t0v = s_tri[ti * 5 + 0];
                    float4 t1v = s_tri[ti * 5 + 1];
                    float4 t2v = s_tri[ti * 5 + 2];
                    // rect-corner z minimum (plane form, conservative slack)
                    float dzdx = t0v.w, dzdy = t1v.w, z0 = t2v.w;
                    float zx = (dzdx >= 0.f) ? wxmin : wxmax;
                    float zy = (dzdy >= 0.f) ? rymin : rymax;
                    float zrmin = fmaf(dzdy, zy, fmaf(dzdx, zx, z0)) - 1e-4f;
                    float zcull = fmaxf(s_tri[ti * 5 + 4].w, zrmin);
                    pass = (zcull <= zbound);
                    if (pass) {
                        // e max over rect at sign-selected corner
                        float y0s = (t0v.x >= 0.f) ? rymax : rymin;
                        float x0s = (t0v.y >= 0.f) ? wxmin : wxmax;
                        float em0 = fmaf(t0v.x, y0s, fmaf(-t0v.y, x0s, t0v.z));
                        float y1s = (t1v.x >= 0.f) ? rymax : rymin;
                        float x1s = (t1v.y >= 0.f) ? wxmin : wxmax;
                        float em1 = fmaf(t1v.x, y1s, fmaf(-t1v.y, x1s, t1v.z));
                        float y2s = (t2v.x >= 0.f) ? rymax : rymin;
                        float x2s = (t2v.y >= 0.f) ? wxmin : wxmax;
                        float em2 = fmaf(t2v.x, y2s, fmaf(-t2v.y, x2s, t2v.z));
                        pass = (em0 >= 0.f) && (em1 >= 0.f) && (em2 >= 0.f);
                    }
                }
            }
            unsigned mask = __ballot_sync(0xffffffffu, pass);
            while (mask) {
                int t = __ffs(mask) - 1;
                mask &= mask - 1;
                t += t0;
                float4 f0 = s_tri[t * 5 + 0];
                float4 f1 = s_tri[t * 5 + 1];
                float4 f2 = s_tri[t * 5 + 2];
                float4 f4 = s_tri[t * 5 + 4];
                float e0b = fmaf(f0.x, gy0, fmaf(-f0.y, gx, f0.z));
                float e1b = fmaf(f1.x, gy0, fmaf(-f1.y, gx, f1.z));
                float e2b = fmaf(f2.x, gy0, fmaf(-f2.y, gx, f2.z));
                float zpb = e0b * f4.x + e1b * f4.y + e2b * f4.z;
                float dzp = f1.w;                    // precomputed dzdy
                int tg = base + t;
#pragma unroll
                for (int r = 0; r < 8; r++) {
                    float rf = (float)r;
                    float e0 = fmaf(rf, f0.x, e0b);
                    float e1 = fmaf(rf, f1.x, e1b);
                    float e2 = fmaf(rf, f2.x, e2b);
                    float zp = fmaf(rf, dzp, zpb);
                    float m  = fminf(fminf(e0, e1), e2);
                    float m2 = fminf(m, zp + 1.0f);      // folds zp >= -1
                    bool upd = (m2 >= 0.f) && (zp < depth[r]);
                    depth[r] = upd ? zp : depth[r];
                    win[r]   = upd ? tg : win[r];
                }
            }
        }
    }

    float2* part = g_part + ((size_t)split * NR + n) * (IMG * IMG);
#pragma unroll
    for (int r = 0; r < 8; r++) {
        int y = r0 + r;
        part[y * IMG + tid] = make_float2(depth[r], __int_as_float(win[r]));
    }
}

// ---------------------------------------------------------------------------
// Kernel B2: merge split partials, resolve winner attrs, texture sample.
// ---------------------------------------------------------------------------
__global__ __launch_bounds__(256) void resolve_kernel(const float* __restrict__ texture)
{
    int gid = blockIdx.x * 256 + threadIdx.x;
    int n = gid >> 14;                 // / (IMG*IMG)
    int pix = gid & (IMG * IMG - 1);
    int px = pix & (IMG - 1);
    int py = pix >> 7;
    int4 rect = g_rect[n];
    if (px < rect.x || px > rect.z || py < rect.y || py > rect.w) return;

    const float2* part = g_part + (size_t)n * (IMG * IMG) + pix;
    float dmin = INFINITY;
    int w = -1;
#pragma unroll
    for (int s = 0; s < NSPLIT; s++) {
        float2 pr = part[(size_t)s * NR * IMG * IMG];
        int wi = __float_as_int(pr.y);
        if (wi >= 0 && pr.x < dmin) { dmin = pr.x; w = wi; }
    }

    int bidx = n & (NB - 1);
    const float* tex = texture + (size_t)bidx * THW * THW * TCH;
    float4 oa, ob;
    float u = 0.f, v = 0.f;
    float mask = 0.f;
    if (w < 0) {
        // background: u=v=0 -> exact tex[0,0] (weights (1,0,0,0) exactly)
        const float4* t00 = (const float4*)tex;
        oa = t00[0]; ob = t00[1];
    } else {
        mask = 1.f;
        float gx = px + 0.5f;
        float gy = py + 0.5f;
        const float4* trih = g_trih + (size_t)n * FMAX * 5;
        const float4* tric = g_tric + (size_t)n * FMAX * 3;
        float4 f0 = trih[w * 5 + 0];
        float4 f1 = trih[w * 5 + 1];
        float4 f2 = trih[w * 5 + 2];
        float4 c0 = tric[w * 3 + 0];
        float4 c1 = tric[w * 3 + 1];
        float4 c2 = tric[w * 3 + 2];
        float e0 = fmaf(f0.x, gy, fmaf(-f0.y, gx, f0.z));
        float e1 = fmaf(f1.x, gy, fmaf(-f1.y, gx, f1.z));
        float e2 = fmaf(f2.x, gy, fmaf(-f2.y, gx, f2.z));
        float b0 = e0 * c0.x, b1 = e1 * c0.x, b2 = e2 * c0.x;
        float pw = b0 * c0.y + b1 * c0.z + b2 * c0.w;
        pw = (fabsf(pw) < 1e-12f) ? 1e-12f : pw;
        float ipw = 1.0f / pw;
        u = (b0 * c1.x + b1 * c1.y + b2 * c1.z) * ipw;
        v = (b0 * c2.x + b1 * c2.y + b2 * c2.z) * ipw;

        float idy = fminf(fmaxf(v, 0.f), 1.f) * 1024.0f;
        float idx = fminf(fmaxf(u, 0.f), 1.f) * 1024.0f;
        float fly = floorf(idy), flx = floorf(idx);
        float fy = idy - fly, fx = idx - flx;
        int i = (int)fly, j = (int)flx;
        int i0 = min(max(i, 0), 1023), j0 = min(max(j, 0), 1023);
        int i1 = min(i + 1, 1023),     j1 = min(j + 1, 1023);
        const float4* t00 = (const float4*)(tex + ((size_t)i0 * 1024 + j0) * 8);
        const float4* t01 = (const float4*)(tex + ((size_t)i0 * 1024 + j1) * 8);
        const float4* t10 = (const float4*)(tex + ((size_t)i1 * 1024 + j0) * 8);
        const float4* t11 = (const float4*)(tex + ((size_t)i1 * 1024 + j1) * 8);
        float w00 = (1.f - fx) * (1.f - fy);
        float w01 = fx * (1.f - fy);
        float w10 = (1.f - fx) * fy;
        float w11 = fx * fy;
        float4 qa00 = t00[0], qb00 = t00[1];
        float4 qa01 = t01[0], qb01 = t01[1];
        float4 qa10 = t10[0], qb10 = t10[1];
        float4 qa11 = t11[0], qb11 = t11[1];
        oa.x = qa00.x * w00 + qa01.x * w01 + qa10.x * w10 + qa11.x * w11;
        oa.y = qa00.y * w00 + qa01.y * w01 + qa10.y * w10 + qa11.y * w11;
        oa.z = qa00.z * w00 + qa01.z * w01 + qa10.z * w10 + qa11.z * w11;
        oa.w = qa00.w * w00 + qa01.w * w01 + qa10.w * w10 + qa11.w * w11;
        ob.x = qb00.x * w00 + qb01.x * w01 + qb10.x * w10 + qb11.x * w11;
        ob.y = qb00.y * w00 + qb01.y * w01 + qb10.y * w10 + qb11.y * w11;
        ob.z = qb00.z * w00 + qb01.z * w01 + qb10.z * w10 + qb11.z * w11;
        ob.w = qb00.w * w00 + qb01.w * w01 + qb10.w * w10 + qb11.w * w11;
    }
    g_rend[(size_t)gid * 2 + 0] = oa;
    g_rend[(size_t)gid * 2 + 1] = ob;
    g_uvm[gid] = make_float4(u, v, mask, ((u + v) > 0.f) ? 1.f : 0.f);
}

// ---------------------------------------------------------------------------
// Kernel C: crop_and_resize (bilinear) + thresholds, one thread per out pixel
// ---------------------------------------------------------------------------
__global__ __launch_bounds__(256) void crop_kernel(const float* __restrict__ bboxes,
                                                   float* __restrict__ out)
{
    int gid = blockIdx.x * 256 + threadIdx.x;
    if (gid >= NR * TGT * TGT) return;
    int n = gid / (TGT * TGT);
    int pix = gid - n * (TGT * TGT);
    int ty = pix / TGT, tx = pix - (pix / TGT) * TGT;
    int b = n & 3, p = n >> 2;
    const float* bx = bboxes + (size_t)(b * NP + p) * 4;
    float y1 = bx[0], x1 = bx[1], y2 = bx[2], x2 = bx[3];
    float stepy = ((y2 - y1) * 127.0f) / 63.0f;
    float stepx = ((x2 - x1) * 127.0f) / 63.0f;
    float ys = y1 * 127.0f + (float)ty * stepy;
    float xs = x1 * 127.0f + (float)tx * stepx;
    bool vy = (ys >= 0.f) && (ys <= 127.f);
    bool vx = (xs >= 0.f) && (xs <= 127.f);
    bool valid = vy && vx;
    float yc = fminf(fmaxf(ys, 0.f), 127.f);
    float xc = fminf(fmaxf(xs, 0.f), 127.f);
    float y0f = floorf(yc), x0f = floorf(xc);
    float fy = yc - y0f, fx = xc - x0f;
    int i0 = (int)y0f, j0 = (int)x0f;
    int i1 = min(i0 + 1, 127), j1 = min(j0 + 1, 127);
    float w00 = (1.f - fy) * (1.f - fx);
    float w01 = (1.f - fy) * fx;
    float w10 = fy * (1.f - fx);
    float w11 = fy * fx;

    size_t ib = (size_t)n * (IMG * IMG);
    float4 m00 = g_uvm[ib + i0 * IMG + j0];
    float4 m01 = g_uvm[ib + i0 * IMG + j1];
    float4 m10 = g_uvm[ib + i1 * IMG + j0];
    float4 m11 = g_uvm[ib + i1 * IMG + j1];
    float4 ra00 = g_rend[(ib + i0 * IMG + j0) * 2],     rb00 = g_rend[(ib + i0 * IMG + j0) * 2 + 1];
    float4 ra01 = g_rend[(ib + i0 * IMG + j1) * 2],     rb01 = g_rend[(ib + i0 * IMG + j1) * 2 + 1];
    float4 ra10 = g_rend[(ib + i1 * IMG + j0) * 2],     rb10 = g_rend[(ib + i1 * IMG + j0) * 2 + 1];
    float4 ra11 = g_rend[(ib + i1 * IMG + j1) * 2],     rb11 = g_rend[(ib + i1 * IMG + j1) * 2 + 1];

    float mnew = m00.w * w00 + m01.w * w01 + m10.w * w10 + m11.w * w11;
    float mold = m00.z * w00 + m01.z * w01 + m10.z * w10 + m11.z * w11;
    float uo   = m00.x * w00 + m01.x * w01 + m10.x * w10 + m11.x * w11;
    float vo   = m00.y * w00 + m01.y * w01 + m10.y * w10 + m11.y * w11;
    float rc[8];
    rc[0] = ra00.x * w00 + ra01.x * w01 + ra10.x * w10 + ra11.x * w11;
    rc[1] = ra00.y * w00 + ra01.y * w01 + ra10.y * w10 + ra11.y * w11;
    rc[2] = ra00.z * w00 + ra01.z * w01 + ra10.z * w10 + ra11.z * w11;
    rc[3] = ra00.w * w00 + ra01.w * w01 + ra10.w * w10 + ra11.w * w11;
    rc[4] = rb00.x * w00 + rb01.x * w01 + rb10.x * w10 + rb11.x * w11;
    rc[5] = rb00.y * w00 + rb01.y * w01 + rb10.y * w10 + rb11.y * w11;
    rc[6] = rb00.z * w00 + rb01.z * w01 + rb10.z * w10 + rb11.z * w11;
    rc[7] = rb00.w * w00 + rb01.w * w01 + rb10.w * w10 + rb11.w * w11;

    float vscale = valid ? 1.0f : 0.0f;
    float4 o0, o1, o2;
    o0.x = (valid && mnew > 0.5f) ? 1.f : 0.f;
    o0.y = rc[0] * vscale;
    o0.z = rc[1] * vscale;
    o0.w = rc[2] * vscale;
    o1.x = rc[3] * vscale;
    o1.y = rc[4] * vscale;
    o1.z = rc[5] * vscale;
    o1.w = rc[6] * vscale;
    o2.x = rc[7] * vscale;
    o2.y = (valid && mold > 0.5f) ? 1.f : 0.f;
    o2.z = uo * vscale;
    o2.w = vo * vscale;
    float4* op = (float4*)(out + (size_t)gid * 12);
    op[0] = o0;
    op[1] = o1;
    op[2] = o2;
}

// ---------------------------------------------------------------------------
extern "C" void kernel_launch(void* const* d_in, const int* in_sizes, int n_in,
                              void* d_out, int out_size)
{
    const float* vertices = (const float*)d_in[0];
    const float* uv_map   = (const float*)d_in[1];
    const int*   faces    = (const int*)d_in[2];
    const float* texture  = (const float*)d_in[3];
    const float* poses    = (const float*)d_in[4];
    const float* bboxes   = (const float*)d_in[5];
    int V = in_sizes[0] / (NB * 3);
    int F = in_sizes[2] / (NB * 3);

    dim3 gV(NR, (V + 255) / 256);
    vertex_kernel<<<gV, 256>>>(vertices, poses, bboxes, V);
    dim3 gF(NR, (F + 255) / 256);
    face_kernel<<<gF, 256>>>(uv_map, faces, V, F);
    dim3 gB(16, NR, NSPLIT);
    raster_kernel<<<gB, 128>>>(F);
    int nfull = NR * IMG * IMG;
    resolve_kernel<<<nfull / 256, 256>>>(texture);
    int npix = NR * TGT * TGT;
    crop_kernel<<<(npix + 255) / 256, 256>>>(bboxes, (float*)d_out);
}